// round 1
// baseline (speedup 1.0000x reference)
#include <cuda_runtime.h>
#include <math.h>

// Problem constants
// x: (b=2, c=512, t=16, h=32, w=32), HEADS=8, d=64, n=hw=1024
#define Bb 2
#define Cc 512
#define Tt 16
#define NN 1024
#define HEADS 8
#define Dd 64
#define BT 32              // b*t
#define C3 1536

// ---------------- scratch (device globals; no allocation) ----------------
__device__ float g_sqkv[BT * C3 * NN];          // 192 MB spatial qkv
__device__ float g_ctx [BT * HEADS * Dd * Dd];  // 4 MB
__device__ float g_sattn[BT * Cc * NN];         // 64 MB spatial attn out (pre-proj)
__device__ float g_h1  [Bb * Cc * Tt * NN];     // 64 MB h1 (b,c,t,n)
__device__ float g_tqkv[Bb * C3 * Tt * NN];     // 192 MB temporal qkv (b,o,t,n)
__device__ float g_attn[Bb * HEADS * Tt * Tt * NN]; // 16 MB temporal attn weights
__device__ float g_tout[Bb * Cc * Tt * NN];     // 64 MB temporal attn out (pre-proj)

// ---------------- generic GEMM: C[g][o][n] = sum_c W[o][c] * X[g][c][n] ----------------
// W row-major [O,K], X strided, optional bias (per o) and residual (same layout as C).
__global__ __launch_bounds__(256) void gemm_wx(
    const float* __restrict__ W,
    const float* __restrict__ X,
    float* __restrict__ C,
    const float* __restrict__ bias,
    const float* __restrict__ res,
    int K, int gDiv,
    long long xOuter, long long xInner, long long xRow,
    long long cOuter, long long cInner, long long cRow)
{
    int g = blockIdx.z;
    long long gq = g / gDiv, gr = g % gDiv;
    const float* Xb = X + gq * xOuter + gr * xInner;
    float*       Cb = C + gq * cOuter + gr * cInner;
    const float* Rb = res ? (res + gq * cOuter + gr * cInner) : nullptr;

    int n0 = blockIdx.x * 64;
    int o0 = blockIdx.y * 64;

    __shared__ float As[16][68];   // [k][m]
    __shared__ float Bs[16][68];   // [k][n]

    int tid = threadIdx.x;
    int tx = tid & 15;             // n micro-col
    int ty = tid >> 4;             // m micro-row

    int ar  = tid >> 2, ac4 = tid & 3;   // A tile load: row 0..63, float4 col 0..3
    int bk  = tid >> 4, bn4 = tid & 15;  // B tile load: k 0..15, float4 n 0..15

    float acc[4][4] = {};

    for (int k0 = 0; k0 < K; k0 += 16) {
        float4 av = *(const float4*)&W[(long long)(o0 + ar) * K + k0 + ac4 * 4];
        As[ac4 * 4 + 0][ar] = av.x;
        As[ac4 * 4 + 1][ar] = av.y;
        As[ac4 * 4 + 2][ar] = av.z;
        As[ac4 * 4 + 3][ar] = av.w;
        float4 bv = *(const float4*)&Xb[(long long)(k0 + bk) * xRow + n0 + bn4 * 4];
        *(float4*)&Bs[bk][bn4 * 4] = bv;
        __syncthreads();
        #pragma unroll
        for (int k = 0; k < 16; k++) {
            float4 a = *(float4*)&As[k][ty * 4];
            float4 b = *(float4*)&Bs[k][tx * 4];
            float aa[4] = {a.x, a.y, a.z, a.w};
            float bb[4] = {b.x, b.y, b.z, b.w};
            #pragma unroll
            for (int i = 0; i < 4; i++)
                #pragma unroll
                for (int j = 0; j < 4; j++)
                    acc[i][j] += aa[i] * bb[j];
        }
        __syncthreads();
    }

    #pragma unroll
    for (int i = 0; i < 4; i++) {
        int o = o0 + ty * 4 + i;
        float bval = bias ? bias[o] : 0.f;
        long long coff = (long long)o * cRow + n0 + tx * 4;
        float4 r = make_float4(0.f, 0.f, 0.f, 0.f);
        if (Rb) r = *(const float4*)&Rb[coff];
        float4 outv;
        outv.x = acc[i][0] + bval + r.x;
        outv.y = acc[i][1] + bval + r.y;
        outv.z = acc[i][2] + bval + r.z;
        outv.w = acc[i][3] + bval + r.w;
        *(float4*)&Cb[coff] = outv;
    }
}

// ---------------- spatial softmaxes ----------------
// q: softmax over d (64, stride NN), then * scale (0.125)
__global__ void softmax_q(float* __restrict__ p)
{
    // grid (NN/128, HEADS, BT), block 128
    int n = blockIdx.x * 128 + threadIdx.x;
    long long base = (long long)blockIdx.z * C3 * NN + (long long)blockIdx.y * Dd * NN + n;
    float m = p[base];
    float s = 1.f;
    for (int d = 1; d < Dd; d++) {
        float v = p[base + (long long)d * NN];
        float nm = fmaxf(m, v);
        s = s * __expf(m - nm) + __expf(v - nm);
        m = nm;
    }
    float inv = 0.125f / s;
    for (int d = 0; d < Dd; d++) {
        long long idx = base + (long long)d * NN;
        p[idx] = __expf(p[idx] - m) * inv;
    }
}

// k: softmax over n (1024 contiguous)
__global__ __launch_bounds__(256) void softmax_k(float* __restrict__ p)
{
    // grid (512 channels, BT), block 256
    float* row = p + (long long)blockIdx.y * C3 * NN + (long long)(Cc + blockIdx.x) * NN;
    int tid = threadIdx.x;
    float v[4];
    float m = -INFINITY;
    #pragma unroll
    for (int k = 0; k < 4; k++) { v[k] = row[tid + 256 * k]; m = fmaxf(m, v[k]); }
    __shared__ float red[8];
    #pragma unroll
    for (int o = 16; o; o >>= 1) m = fmaxf(m, __shfl_xor_sync(0xffffffffu, m, o));
    if ((tid & 31) == 0) red[tid >> 5] = m;
    __syncthreads();
    m = red[0];
    #pragma unroll
    for (int wv = 1; wv < 8; wv++) m = fmaxf(m, red[wv]);
    __syncthreads();
    float s = 0.f;
    #pragma unroll
    for (int k = 0; k < 4; k++) { v[k] = __expf(v[k] - m); s += v[k]; }
    #pragma unroll
    for (int o = 16; o; o >>= 1) s += __shfl_xor_sync(0xffffffffu, s, o);
    if ((tid & 31) == 0) red[tid >> 5] = s;
    __syncthreads();
    s = 0.f;
    #pragma unroll
    for (int wv = 0; wv < 8; wv++) s += red[wv];
    float inv = 1.f / s;
    #pragma unroll
    for (int k = 0; k < 4; k++) row[tid + 256 * k] = v[k] * inv;
}

// ---------------- spatial: ctx[d][e] = sum_n k[d][n] * v[e][n] ----------------
__global__ __launch_bounds__(256) void ctx_kernel(const float* __restrict__ qkv,
                                                  float* __restrict__ ctx)
{
    // grid (HEADS, BT)
    int h = blockIdx.x, bt = blockIdx.y;
    const float* kbase = qkv + (long long)bt * C3 * NN + (long long)(Cc + h * Dd) * NN;
    const float* vbase = qkv + (long long)bt * C3 * NN + (long long)(2 * Cc + h * Dd) * NN;
    __shared__ float Ks[64][68];   // [nn][d]
    __shared__ float Vs[64][68];   // [nn][e]
    int tid = threadIdx.x;
    int tx = tid & 15, ty = tid >> 4;
    float acc[4][4] = {};
    for (int n0 = 0; n0 < NN; n0 += 64) {
        #pragma unroll
        for (int l = 0; l < 16; l++) {
            int idx = l * 256 + tid;
            int d = idx >> 6, nn = idx & 63;
            Ks[nn][d] = kbase[(long long)d * NN + n0 + nn];
            Vs[nn][d] = vbase[(long long)d * NN + n0 + nn];
        }
        __syncthreads();
        #pragma unroll
        for (int nn = 0; nn < 64; nn++) {
            float4 a = *(float4*)&Ks[nn][ty * 4];
            float4 b = *(float4*)&Vs[nn][tx * 4];
            float aa[4] = {a.x, a.y, a.z, a.w};
            float bb[4] = {b.x, b.y, b.z, b.w};
            #pragma unroll
            for (int i = 0; i < 4; i++)
                #pragma unroll
                for (int j = 0; j < 4; j++)
                    acc[i][j] += aa[i] * bb[j];
        }
        __syncthreads();
    }
    float* cb = ctx + ((long long)bt * HEADS + h) * Dd * Dd;
    #pragma unroll
    for (int i = 0; i < 4; i++) {
        float4 ov = make_float4(acc[i][0], acc[i][1], acc[i][2], acc[i][3]);
        *(float4*)&cb[(ty * 4 + i) * Dd + tx * 4] = ov;
    }
}

// ---------------- spatial: out[e][n] = sum_d ctx[d][e] * q[d][n] ----------------
__global__ __launch_bounds__(256) void attn_apply_kernel(const float* __restrict__ qkv,
                                                         const float* __restrict__ ctx,
                                                         float* __restrict__ out)
{
    // grid (NN/64, HEADS, BT)
    int n0 = blockIdx.x * 64, h = blockIdx.y, bt = blockIdx.z;
    const float* qbase = qkv + (long long)bt * C3 * NN + (long long)(h * Dd) * NN;
    const float* cb = ctx + ((long long)bt * HEADS + h) * Dd * Dd;
    __shared__ float As[64][68];   // [d][e]
    __shared__ float Bs[64][68];   // [d][nn]
    int tid = threadIdx.x;
    int tx = tid & 15, ty = tid >> 4;
    #pragma unroll
    for (int l = 0; l < 16; l++) {
        int idx = l * 256 + tid;
        int d = idx >> 6, e = idx & 63;
        As[d][e] = cb[idx];
        Bs[d][e] = qbase[(long long)d * NN + n0 + e];
    }
    __syncthreads();
    float acc[4][4] = {};
    #pragma unroll
    for (int d = 0; d < 64; d++) {
        float4 a = *(float4*)&As[d][ty * 4];
        float4 b = *(float4*)&Bs[d][tx * 4];
        float aa[4] = {a.x, a.y, a.z, a.w};
        float bb[4] = {b.x, b.y, b.z, b.w};
        #pragma unroll
        for (int i = 0; i < 4; i++)
            #pragma unroll
            for (int j = 0; j < 4; j++)
                acc[i][j] += aa[i] * bb[j];
    }
    float* ob = out + (long long)bt * Cc * NN + (long long)(h * Dd) * NN;
    #pragma unroll
    for (int i = 0; i < 4; i++) {
        float4 ov = make_float4(acc[i][0], acc[i][1], acc[i][2], acc[i][3]);
        *(float4*)&ob[(long long)(ty * 4 + i) * NN + n0 + tx * 4] = ov;
    }
}

// ---------------- temporal attention ----------------
#define ST 8   // s-tile
// Pass A: sim + softmax -> attn weights. layout attn[((b*8+h)*16+i)*16+j][s]
__global__ __launch_bounds__(128) void temporal_sim(const float* __restrict__ tqkv,
                                                    float* __restrict__ attn)
{
    // grid (NN/ST, HEADS, Bb), block 128 (8 s x 16 i)
    int b = blockIdx.z, hh = blockIdx.y;
    int s0 = blockIdx.x * ST;
    __shared__ float ks[16 * 64 * (ST + 1)];   // [(j*64+d)*(ST+1) + s]
    const float* kb = tqkv + ((long long)b * C3 + Cc + hh * Dd) * (Tt * NN);
    int tid = threadIdx.x;
    #pragma unroll
    for (int l = 0; l < (16 * 64 * ST) / 128; l++) {
        int idx = l * 128 + tid;
        int s = idx & (ST - 1);
        int rest = idx >> 3;            // j*64+d
        int d = rest & 63, j = rest >> 6;
        ks[rest * (ST + 1) + s] = kb[(long long)d * (Tt * NN) + j * NN + s0 + s];
    }
    __syncthreads();
    int sl = tid & (ST - 1);
    int i  = tid >> 3;
    const float* qb = tqkv + ((long long)b * C3 + hh * Dd) * (Tt * NN) + (long long)i * NN + s0 + sl;
    float acc[16];
    #pragma unroll
    for (int j = 0; j < 16; j++) acc[j] = 0.f;
    for (int d = 0; d < 64; d++) {
        float qv = qb[(long long)d * (Tt * NN)] * 0.125f;
        #pragma unroll
        for (int j = 0; j < 16; j++)
            acc[j] += qv * ks[(j * 64 + d) * (ST + 1) + sl];
    }
    float m = acc[0];
    #pragma unroll
    for (int j = 1; j < 16; j++) m = fmaxf(m, acc[j]);
    float sum = 0.f;
    #pragma unroll
    for (int j = 0; j < 16; j++) { acc[j] = __expf(acc[j] - m); sum += acc[j]; }
    float inv = 1.f / sum;
    float* ab = attn + (((long long)b * HEADS + hh) * Tt + i) * Tt * NN + s0 + sl;
    #pragma unroll
    for (int j = 0; j < 16; j++)
        ab[(long long)j * NN] = acc[j] * inv;
}

// Pass B: out[c=h*64+d][t=i][s] = sum_j attn[i][j] * v[j][d]
__global__ __launch_bounds__(128) void temporal_out(const float* __restrict__ tqkv,
                                                    const float* __restrict__ attn,
                                                    float* __restrict__ out)
{
    // grid (NN/ST, HEADS, Bb), block 128 (8 s x 16 dgrp)
    int b = blockIdx.z, hh = blockIdx.y;
    int s0 = blockIdx.x * ST;
    __shared__ float vs[16 * 64 * (ST + 1)];
    const float* vb = tqkv + ((long long)b * C3 + 2 * Cc + hh * Dd) * (Tt * NN);
    int tid = threadIdx.x;
    #pragma unroll
    for (int l = 0; l < (16 * 64 * ST) / 128; l++) {
        int idx = l * 128 + tid;
        int s = idx & (ST - 1);
        int rest = idx >> 3;
        int d = rest & 63, j = rest >> 6;
        vs[rest * (ST + 1) + s] = vb[(long long)d * (Tt * NN) + j * NN + s0 + s];
    }
    __syncthreads();
    int sl = tid & (ST - 1);
    int dg = tid >> 3;                // 0..15 -> d = dg*4..dg*4+3
    const float* ab = attn + ((long long)b * HEADS + hh) * (Tt * Tt) * NN + s0 + sl;
    float* ob = out + ((long long)b * Cc + hh * Dd + dg * 4) * (Tt * NN) + s0 + sl;
    for (int i = 0; i < 16; i++) {
        float a0 = 0.f, a1 = 0.f, a2 = 0.f, a3 = 0.f;
        #pragma unroll
        for (int j = 0; j < 16; j++) {
            float av = ab[(long long)(i * 16 + j) * NN];
            a0 += av * vs[(j * 64 + dg * 4 + 0) * (ST + 1) + sl];
            a1 += av * vs[(j * 64 + dg * 4 + 1) * (ST + 1) + sl];
            a2 += av * vs[(j * 64 + dg * 4 + 2) * (ST + 1) + sl];
            a3 += av * vs[(j * 64 + dg * 4 + 3) * (ST + 1) + sl];
        }
        long long t_off = (long long)i * NN;
        ob[t_off + 0 * (long long)(Tt * NN)] = a0;
        ob[t_off + 1 * (long long)(Tt * NN)] = a1;
        ob[t_off + 2 * (long long)(Tt * NN)] = a2;
        ob[t_off + 3 * (long long)(Tt * NN)] = a3;
    }
}

// ---------------- launch ----------------
extern "C" void kernel_launch(void* const* d_in, const int* in_sizes, int n_in,
                              void* d_out, int out_size)
{
    const float* x      = (const float*)d_in[0];
    const float* w_sqkv = (const float*)d_in[1];
    const float* w_sout = (const float*)d_in[2];
    const float* b_sout = (const float*)d_in[3];
    const float* w_tqkv = (const float*)d_in[4];
    const float* w_tout = (const float*)d_in[5];
    float* out = (float*)d_out;

    float *sqkv, *ctx, *sattn, *h1, *tqkv, *attn, *tout;
    cudaGetSymbolAddress((void**)&sqkv,  g_sqkv);
    cudaGetSymbolAddress((void**)&ctx,   g_ctx);
    cudaGetSymbolAddress((void**)&sattn, g_sattn);
    cudaGetSymbolAddress((void**)&h1,    g_h1);
    cudaGetSymbolAddress((void**)&tqkv,  g_tqkv);
    cudaGetSymbolAddress((void**)&attn,  g_attn);
    cudaGetSymbolAddress((void**)&tout,  g_tout);

    const long long TN = (long long)Tt * NN;           // 16384
    const long long XB = (long long)Cc * TN;           // 8388608 (b stride of x / h1 / out)

    // 1) spatial qkv: per bt, (1536x512) x (512x1024)
    gemm_wx<<<dim3(NN / 64, C3 / 64, BT), 256>>>(
        w_sqkv, x, sqkv, nullptr, nullptr,
        Cc, Tt,
        XB, NN, TN,                                     // X = x[b][c][t][n]
        (long long)Tt * C3 * NN, (long long)C3 * NN, NN // C = sqkv[bt][o][n]
    );
    // 2) q softmax over d, * scale
    softmax_q<<<dim3(NN / 128, HEADS, BT), 128>>>(sqkv);
    // 3) k softmax over n
    softmax_k<<<dim3(Cc, BT), 256>>>(sqkv);
    // 4) ctx = k v^T
    ctx_kernel<<<dim3(HEADS, BT), 256>>>(sqkv, ctx);
    // 5) out = ctx^T q
    attn_apply_kernel<<<dim3(NN / 64, HEADS, BT), 256>>>(sqkv, ctx, sattn);
    // 6) spatial out proj + bias -> h1[b][c][t][n]
    gemm_wx<<<dim3(NN / 64, Cc / 64, BT), 256>>>(
        w_sout, sattn, h1, b_sout, nullptr,
        Cc, Tt,
        (long long)Tt * Cc * NN, (long long)Cc * NN, NN, // X = sattn[bt][c][n]
        XB, NN, TN                                       // C = h1[b][o][t][n]
    );
    // 7) temporal qkv: per b, (1536x512) x (512x16384)
    gemm_wx<<<dim3((Tt * NN) / 64, C3 / 64, Bb), 256>>>(
        w_tqkv, h1, tqkv, nullptr, nullptr,
        Cc, 1,
        XB, 0, TN,                                       // X = h1[b][c][tn]
        (long long)C3 * TN, 0, TN                        // C = tqkv[b][o][tn]
    );
    // 8) temporal sim + softmax
    temporal_sim<<<dim3(NN / ST, HEADS, Bb), 128>>>(tqkv, attn);
    // 9) temporal attn @ v
    temporal_out<<<dim3(NN / ST, HEADS, Bb), 128>>>(tqkv, attn, tout);
    // 10) temporal out proj + residual -> d_out
    gemm_wx<<<dim3((Tt * NN) / 64, Cc / 64, Bb), 256>>>(
        w_tout, tout, out, nullptr, x,
        Cc, 1,
        XB, 0, TN,                                       // X = tout[b][c][tn]
        XB, 0, TN                                        // C = out[b][o][tn]
    );
}

// round 2
// speedup vs baseline: 4.5719x; 4.5719x over previous
#include <cuda_runtime.h>
#include <cuda_bf16.h>
#include <math.h>
#include <stdint.h>

#define Bb 2
#define Cc 512
#define Tt 16
#define NN 1024
#define HEADS 8
#define Dd 64
#define BT 32
#define C3 1536

// ---------------- scratch (device globals) ----------------
__device__ __align__(16) __nv_bfloat16 g_wsqkv_t[Cc * C3];
__device__ __align__(16) __nv_bfloat16 g_wsout_t[Cc * Cc];
__device__ __align__(16) __nv_bfloat16 g_wtqkv_t[Cc * C3];
__device__ __align__(16) __nv_bfloat16 g_wtout_t[Cc * Cc];
__device__ __align__(16) __nv_bfloat16 g_xbf[Bb * Cc * Tt * NN];
__device__ __align__(16) float         g_sqkv[BT * C3 * NN];
__device__ __align__(16) float         g_ctx [BT * HEADS * Dd * Dd];
__device__ __align__(16) __nv_bfloat16 g_sattn_bf[BT * Cc * NN];
__device__ __align__(16) __nv_bfloat16 g_h1_bf[Bb * Cc * Tt * NN];
__device__ __align__(16) float         g_tqkv[Bb * C3 * Tt * NN];
__device__ __align__(16) float         g_attnw[Bb * HEADS * Tt * Tt * NN];
__device__ __align__(16) __nv_bfloat16 g_tout_bf[Bb * Cc * Tt * NN];

// ---------------- helpers ----------------
__device__ __forceinline__ uint32_t smem_u32(const void* p) {
    uint32_t a;
    asm("{ .reg .u64 t; cvta.to.shared.u64 t, %1; cvt.u32.u64 %0, t; }" : "=r"(a) : "l"(p));
    return a;
}
#define CP_ASYNC(dst, src) asm volatile("cp.async.cg.shared.global [%0],[%1],16;\n" :: "r"(dst), "l"(src) : "memory")
#define CP_COMMIT()        asm volatile("cp.async.commit_group;\n" ::: "memory")
#define CP_WAIT0()         asm volatile("cp.async.wait_group 0;\n" ::: "memory")

// ---------------- conversions ----------------
__global__ void f2b_kernel(const float* __restrict__ in, __nv_bfloat16* __restrict__ out, int n)
{
    int i = (blockIdx.x * blockDim.x + threadIdx.x) * 4;
    if (i < n) {
        float4 v = *(const float4*)(in + i);
        __nv_bfloat162 p0 = __floats2bfloat162_rn(v.x, v.y);
        __nv_bfloat162 p1 = __floats2bfloat162_rn(v.z, v.w);
        uint2 u;
        u.x = *(uint32_t*)&p0;
        u.y = *(uint32_t*)&p1;
        *(uint2*)(out + i) = u;
    }
}

// W[O][K] fp32 -> Wt[K][O] bf16
__global__ void transpose_w_kernel(const float* __restrict__ in, __nv_bfloat16* __restrict__ out,
                                   int O, int K)
{
    int idx = blockIdx.x * blockDim.x + threadIdx.x;
    if (idx < O * K) {
        int o = idx % O;
        int k = idx / O;
        out[idx] = __float2bfloat16(in[(long long)o * K + k]);
    }
}

// ---------------- bf16 tensor-core GEMM ----------------
// C[g][o][n] = sum_k Wt[k][o] * X[g][k][n]   (both operands k-major in smem)
// BM=128, BN=128, BK=32; 256 threads = 8 warps (2 m x 4 n), warp tile 64x32.
__global__ __launch_bounds__(256, 2) void gemm_bf16(
    const __nv_bfloat16* __restrict__ Wt,   // [K][ldA]
    const __nv_bfloat16* __restrict__ X,
    float* __restrict__ Cf,                 // fp32 out (if Cb == null)
    __nv_bfloat16* __restrict__ Cb,         // bf16 out (if non-null)
    const float* __restrict__ bias,
    const float* __restrict__ res,
    int K, int ldA, int gDiv,
    long long xOuter, long long xInner, long long xRow,
    long long cOuter, long long cInner, long long cRow)
{
    __shared__ __nv_bfloat16 As[2][32][128];
    __shared__ __nv_bfloat16 Bs[2][32][128];

    int g = blockIdx.z;
    long long gq = g / gDiv, gr = g % gDiv;
    const __nv_bfloat16* Xb = X + gq * xOuter + gr * xInner;
    long long cbase = gq * cOuter + gr * cInner;

    int n0 = blockIdx.x * 128;
    int o0 = blockIdx.y * 128;

    int tid = threadIdx.x;
    int lane = tid & 31, warp = tid >> 5;
    int wm = warp >> 2, wn = warp & 3;

    uint32_t asb = smem_u32(&As[0][0][0]);
    uint32_t bsb = smem_u32(&Bs[0][0][0]);

    float acc[4][4][4];
    #pragma unroll
    for (int a = 0; a < 4; a++)
        #pragma unroll
        for (int b = 0; b < 4; b++)
            #pragma unroll
            for (int c = 0; c < 4; c++) acc[a][b][c] = 0.f;

    int nkt = K / 32;

    // issue tile kt into buffer buf
    #define ISSUE_TILE(kt, buf) do {                                                   \
        int k0_ = (kt) * 32;                                                           \
        _Pragma("unroll")                                                              \
        for (int i_ = 0; i_ < 2; i_++) {                                               \
            int idx_ = tid + 256 * i_;                                                 \
            int row_ = idx_ >> 4, ch_ = idx_ & 15;                                     \
            const __nv_bfloat16* sA = Wt + (long long)(k0_ + row_) * ldA + o0 + ch_ * 8; \
            uint32_t dA = asb + (buf) * 8192 + row_ * 256 + (((ch_) ^ (row_ & 7)) << 4); \
            CP_ASYNC(dA, sA);                                                          \
            const __nv_bfloat16* sB = Xb + (long long)(k0_ + row_) * xRow + n0 + ch_ * 8; \
            uint32_t dB = bsb + (buf) * 8192 + row_ * 256 + (((ch_) ^ (row_ & 7)) << 4); \
            CP_ASYNC(dB, sB);                                                          \
        }                                                                              \
    } while (0)

    ISSUE_TILE(0, 0);
    CP_COMMIT();

    int r7 = lane & 7, sub = lane >> 3;
    int brow_lo = lane & 15;

    for (int kt = 0; kt < nkt; kt++) {
        CP_WAIT0();
        __syncthreads();
        if (kt + 1 < nkt) {
            ISSUE_TILE(kt + 1, (kt + 1) & 1);
            CP_COMMIT();
        }
        int buf = kt & 1;
        uint32_t abase = asb + buf * 8192;
        uint32_t bbase = bsb + buf * 8192;

        #pragma unroll
        for (int ks = 0; ks < 2; ks++) {
            uint32_t af[4][4];
            uint32_t bf_[4][2];
            #pragma unroll
            for (int mt = 0; mt < 4; mt++) {
                int krow = ks * 16 + r7 + ((sub >> 1) << 3);
                int mcol = wm * 64 + mt * 16 + ((sub & 1) << 3);
                uint32_t addr = abase + krow * 256 + ((((mcol >> 3)) ^ (krow & 7)) << 4);
                asm volatile("ldmatrix.sync.aligned.m8n8.x4.trans.shared.b16 {%0,%1,%2,%3},[%4];"
                             : "=r"(af[mt][0]), "=r"(af[mt][1]), "=r"(af[mt][2]), "=r"(af[mt][3])
                             : "r"(addr));
            }
            #pragma unroll
            for (int nt = 0; nt < 4; nt++) {
                int brow = ks * 16 + brow_lo;
                int ncol = wn * 32 + nt * 8;
                uint32_t addr = bbase + brow * 256 + ((((ncol >> 3)) ^ (brow & 7)) << 4);
                asm volatile("ldmatrix.sync.aligned.m8n8.x2.trans.shared.b16 {%0,%1},[%2];"
                             : "=r"(bf_[nt][0]), "=r"(bf_[nt][1])
                             : "r"(addr));
            }
            #pragma unroll
            for (int mt = 0; mt < 4; mt++)
                #pragma unroll
                for (int nt = 0; nt < 4; nt++) {
                    asm volatile(
                        "mma.sync.aligned.m16n8k16.row.col.f32.bf16.bf16.f32 "
                        "{%0,%1,%2,%3},{%4,%5,%6,%7},{%8,%9},{%0,%1,%2,%3};"
                        : "+f"(acc[mt][nt][0]), "+f"(acc[mt][nt][1]),
                          "+f"(acc[mt][nt][2]), "+f"(acc[mt][nt][3])
                        : "r"(af[mt][0]), "r"(af[mt][1]), "r"(af[mt][2]), "r"(af[mt][3]),
                          "r"(bf_[nt][0]), "r"(bf_[nt][1]));
                }
        }
    }

    // epilogue
    int g4 = lane >> 2, t4 = lane & 3;
    #pragma unroll
    for (int mt = 0; mt < 4; mt++) {
        #pragma unroll
        for (int nt = 0; nt < 4; nt++) {
            int orow = o0 + wm * 64 + mt * 16 + g4;
            int col  = n0 + wn * 32 + nt * 8 + t4 * 2;
            long long off0 = cbase + (long long)orow * cRow + col;
            long long off1 = off0 + 8 * cRow;
            float b0 = bias ? bias[orow] : 0.f;
            float b1 = bias ? bias[orow + 8] : 0.f;
            float* a = acc[mt][nt];
            if (Cb) {
                __nv_bfloat162 v0 = __floats2bfloat162_rn(a[0] + b0, a[1] + b0);
                __nv_bfloat162 v1 = __floats2bfloat162_rn(a[2] + b1, a[3] + b1);
                *reinterpret_cast<__nv_bfloat162*>(Cb + off0) = v0;
                *reinterpret_cast<__nv_bfloat162*>(Cb + off1) = v1;
            } else {
                float2 r0 = make_float2(0.f, 0.f), r1 = make_float2(0.f, 0.f);
                if (res) { r0 = *(const float2*)(res + off0); r1 = *(const float2*)(res + off1); }
                float2 o0v = make_float2(a[0] + b0 + r0.x, a[1] + b0 + r0.y);
                float2 o1v = make_float2(a[2] + b1 + r1.x, a[3] + b1 + r1.y);
                *(float2*)(Cf + off0) = o0v;
                *(float2*)(Cf + off1) = o1v;
            }
        }
    }
    #undef ISSUE_TILE
}

// ---------------- spatial softmaxes ----------------
__global__ void softmax_q(float* __restrict__ p)
{
    int n = blockIdx.x * 128 + threadIdx.x;
    long long base = (long long)blockIdx.z * C3 * NN + (long long)blockIdx.y * Dd * NN + n;
    float m = p[base];
    float s = 1.f;
    for (int d = 1; d < Dd; d++) {
        float v = p[base + (long long)d * NN];
        float nm = fmaxf(m, v);
        s = s * __expf(m - nm) + __expf(v - nm);
        m = nm;
    }
    float inv = 0.125f / s;
    for (int d = 0; d < Dd; d++) {
        long long idx = base + (long long)d * NN;
        p[idx] = __expf(p[idx] - m) * inv;
    }
}

__global__ __launch_bounds__(256) void softmax_k(float* __restrict__ p)
{
    float* row = p + (long long)blockIdx.y * C3 * NN + (long long)(Cc + blockIdx.x) * NN;
    int tid = threadIdx.x;
    float v[4];
    float m = -INFINITY;
    #pragma unroll
    for (int k = 0; k < 4; k++) { v[k] = row[tid + 256 * k]; m = fmaxf(m, v[k]); }
    __shared__ float red[8];
    #pragma unroll
    for (int o = 16; o; o >>= 1) m = fmaxf(m, __shfl_xor_sync(0xffffffffu, m, o));
    if ((tid & 31) == 0) red[tid >> 5] = m;
    __syncthreads();
    m = red[0];
    #pragma unroll
    for (int wv = 1; wv < 8; wv++) m = fmaxf(m, red[wv]);
    __syncthreads();
    float s = 0.f;
    #pragma unroll
    for (int k = 0; k < 4; k++) { v[k] = __expf(v[k] - m); s += v[k]; }
    #pragma unroll
    for (int o = 16; o; o >>= 1) s += __shfl_xor_sync(0xffffffffu, s, o);
    if ((tid & 31) == 0) red[tid >> 5] = s;
    __syncthreads();
    s = 0.f;
    #pragma unroll
    for (int wv = 0; wv < 8; wv++) s += red[wv];
    float inv = 1.f / s;
    #pragma unroll
    for (int k = 0; k < 4; k++) row[tid + 256 * k] = v[k] * inv;
}

// ---------------- spatial: ctx[d][e] = sum_n k[d][n] * v[e][n] ----------------
__global__ __launch_bounds__(256) void ctx_kernel(const float* __restrict__ qkv,
                                                  float* __restrict__ ctx)
{
    int h = blockIdx.x, bt = blockIdx.y;
    const float* kbase = qkv + (long long)bt * C3 * NN + (long long)(Cc + h * Dd) * NN;
    const float* vbase = qkv + (long long)bt * C3 * NN + (long long)(2 * Cc + h * Dd) * NN;
    __shared__ float Ks[64][68];
    __shared__ float Vs[64][68];
    int tid = threadIdx.x;
    int tx = tid & 15, ty = tid >> 4;
    float acc[4][4] = {};
    for (int n0 = 0; n0 < NN; n0 += 64) {
        #pragma unroll
        for (int l = 0; l < 16; l++) {
            int idx = l * 256 + tid;
            int d = idx >> 6, nn = idx & 63;
            Ks[nn][d] = kbase[(long long)d * NN + n0 + nn];
            Vs[nn][d] = vbase[(long long)d * NN + n0 + nn];
        }
        __syncthreads();
        #pragma unroll
        for (int nn = 0; nn < 64; nn++) {
            float4 a = *(float4*)&Ks[nn][ty * 4];
            float4 b = *(float4*)&Vs[nn][tx * 4];
            float aa[4] = {a.x, a.y, a.z, a.w};
            float bb[4] = {b.x, b.y, b.z, b.w};
            #pragma unroll
            for (int i = 0; i < 4; i++)
                #pragma unroll
                for (int j = 0; j < 4; j++)
                    acc[i][j] += aa[i] * bb[j];
        }
        __syncthreads();
    }
    float* cb = ctx + ((long long)bt * HEADS + h) * Dd * Dd;
    #pragma unroll
    for (int i = 0; i < 4; i++) {
        float4 ov = make_float4(acc[i][0], acc[i][1], acc[i][2], acc[i][3]);
        *(float4*)&cb[(ty * 4 + i) * Dd + tx * 4] = ov;
    }
}

// ---------------- spatial: out[e][n] = sum_d ctx[d][e] * q[d][n]  (bf16 out) ----------------
__global__ __launch_bounds__(256) void attn_apply_kernel(const float* __restrict__ qkv,
                                                         const float* __restrict__ ctx,
                                                         __nv_bfloat16* __restrict__ out)
{
    int n0 = blockIdx.x * 64, h = blockIdx.y, bt = blockIdx.z;
    const float* qbase = qkv + (long long)bt * C3 * NN + (long long)(h * Dd) * NN;
    const float* cb = ctx + ((long long)bt * HEADS + h) * Dd * Dd;
    __shared__ float As[64][68];
    __shared__ float Bs[64][68];
    int tid = threadIdx.x;
    int tx = tid & 15, ty = tid >> 4;
    #pragma unroll
    for (int l = 0; l < 16; l++) {
        int idx = l * 256 + tid;
        int d = idx >> 6, e = idx & 63;
        As[d][e] = cb[idx];
        Bs[d][e] = qbase[(long long)d * NN + n0 + e];
    }
    __syncthreads();
    float acc[4][4] = {};
    #pragma unroll
    for (int d = 0; d < 64; d++) {
        float4 a = *(float4*)&As[d][ty * 4];
        float4 b = *(float4*)&Bs[d][tx * 4];
        float aa[4] = {a.x, a.y, a.z, a.w};
        float bb[4] = {b.x, b.y, b.z, b.w};
        #pragma unroll
        for (int i = 0; i < 4; i++)
            #pragma unroll
            for (int j = 0; j < 4; j++)
                acc[i][j] += aa[i] * bb[j];
    }
    __nv_bfloat16* ob = out + (long long)bt * Cc * NN + (long long)(h * Dd) * NN;
    #pragma unroll
    for (int i = 0; i < 4; i++) {
        __nv_bfloat162 p0 = __floats2bfloat162_rn(acc[i][0], acc[i][1]);
        __nv_bfloat162 p1 = __floats2bfloat162_rn(acc[i][2], acc[i][3]);
        long long off = (long long)(ty * 4 + i) * NN + n0 + tx * 4;
        *reinterpret_cast<__nv_bfloat162*>(ob + off) = p0;
        *reinterpret_cast<__nv_bfloat162*>(ob + off + 2) = p1;
    }
}

// ---------------- temporal attention ----------------
#define ST 8
__global__ __launch_bounds__(128) void temporal_sim(const float* __restrict__ tqkv,
                                                    float* __restrict__ attn)
{
    int b = blockIdx.z, hh = blockIdx.y;
    int s0 = blockIdx.x * ST;
    __shared__ float ks[16 * 64 * (ST + 1)];
    const float* kb = tqkv + ((long long)b * C3 + Cc + hh * Dd) * (Tt * NN);
    int tid = threadIdx.x;
    #pragma unroll
    for (int l = 0; l < (16 * 64 * ST) / 128; l++) {
        int idx = l * 128 + tid;
        int s = idx & (ST - 1);
        int rest = idx >> 3;
        int d = rest & 63, j = rest >> 6;
        ks[rest * (ST + 1) + s] = kb[(long long)d * (Tt * NN) + j * NN + s0 + s];
    }
    __syncthreads();
    int sl = tid & (ST - 1);
    int i  = tid >> 3;
    const float* qb = tqkv + ((long long)b * C3 + hh * Dd) * (Tt * NN) + (long long)i * NN + s0 + sl;
    float acc[16];
    #pragma unroll
    for (int j = 0; j < 16; j++) acc[j] = 0.f;
    for (int d = 0; d < 64; d++) {
        float qv = qb[(long long)d * (Tt * NN)] * 0.125f;
        #pragma unroll
        for (int j = 0; j < 16; j++)
            acc[j] += qv * ks[(j * 64 + d) * (ST + 1) + sl];
    }
    float m = acc[0];
    #pragma unroll
    for (int j = 1; j < 16; j++) m = fmaxf(m, acc[j]);
    float sum = 0.f;
    #pragma unroll
    for (int j = 0; j < 16; j++) { acc[j] = __expf(acc[j] - m); sum += acc[j]; }
    float inv = 1.f / sum;
    float* ab = attn + (((long long)b * HEADS + hh) * Tt + i) * Tt * NN + s0 + sl;
    #pragma unroll
    for (int j = 0; j < 16; j++)
        ab[(long long)j * NN] = acc[j] * inv;
}

__global__ __launch_bounds__(128) void temporal_out(const float* __restrict__ tqkv,
                                                    const float* __restrict__ attn,
                                                    __nv_bfloat16* __restrict__ out)
{
    int b = blockIdx.z, hh = blockIdx.y;
    int s0 = blockIdx.x * ST;
    __shared__ float vs[16 * 64 * (ST + 1)];
    const float* vb = tqkv + ((long long)b * C3 + 2 * Cc + hh * Dd) * (Tt * NN);
    int tid = threadIdx.x;
    #pragma unroll
    for (int l = 0; l < (16 * 64 * ST) / 128; l++) {
        int idx = l * 128 + tid;
        int s = idx & (ST - 1);
        int rest = idx >> 3;
        int d = rest & 63, j = rest >> 6;
        vs[rest * (ST + 1) + s] = vb[(long long)d * (Tt * NN) + j * NN + s0 + s];
    }
    __syncthreads();
    int sl = tid & (ST - 1);
    int dg = tid >> 3;
    const float* ab = attn + ((long long)b * HEADS + hh) * (Tt * Tt) * NN + s0 + sl;
    __nv_bfloat16* ob = out + ((long long)b * Cc + hh * Dd + dg * 4) * (Tt * NN) + s0 + sl;
    for (int i = 0; i < 16; i++) {
        float a0 = 0.f, a1 = 0.f, a2 = 0.f, a3 = 0.f;
        #pragma unroll
        for (int j = 0; j < 16; j++) {
            float av = ab[(long long)(i * 16 + j) * NN];
            a0 += av * vs[(j * 64 + dg * 4 + 0) * (ST + 1) + sl];
            a1 += av * vs[(j * 64 + dg * 4 + 1) * (ST + 1) + sl];
            a2 += av * vs[(j * 64 + dg * 4 + 2) * (ST + 1) + sl];
            a3 += av * vs[(j * 64 + dg * 4 + 3) * (ST + 1) + sl];
        }
        long long t_off = (long long)i * NN;
        ob[t_off + 0 * (long long)(Tt * NN)] = __float2bfloat16(a0);
        ob[t_off + 1 * (long long)(Tt * NN)] = __float2bfloat16(a1);
        ob[t_off + 2 * (long long)(Tt * NN)] = __float2bfloat16(a2);
        ob[t_off + 3 * (long long)(Tt * NN)] = __float2bfloat16(a3);
    }
}

// ---------------- launch ----------------
extern "C" void kernel_launch(void* const* d_in, const int* in_sizes, int n_in,
                              void* d_out, int out_size)
{
    const float* x      = (const float*)d_in[0];
    const float* w_sqkv = (const float*)d_in[1];
    const float* w_sout = (const float*)d_in[2];
    const float* b_sout = (const float*)d_in[3];
    const float* w_tqkv = (const float*)d_in[4];
    const float* w_tout = (const float*)d_in[5];
    float* out = (float*)d_out;

    __nv_bfloat16 *wsqkv_t, *wsout_t, *wtqkv_t, *wtout_t, *xbf, *sattn_bf, *h1_bf, *tout_bf;
    float *sqkv, *ctx, *tqkv, *attnw;
    cudaGetSymbolAddress((void**)&wsqkv_t, g_wsqkv_t);
    cudaGetSymbolAddress((void**)&wsout_t, g_wsout_t);
    cudaGetSymbolAddress((void**)&wtqkv_t, g_wtqkv_t);
    cudaGetSymbolAddress((void**)&wtout_t, g_wtout_t);
    cudaGetSymbolAddress((void**)&xbf,     g_xbf);
    cudaGetSymbolAddress((void**)&sqkv,    g_sqkv);
    cudaGetSymbolAddress((void**)&ctx,     g_ctx);
    cudaGetSymbolAddress((void**)&sattn_bf,g_sattn_bf);
    cudaGetSymbolAddress((void**)&h1_bf,   g_h1_bf);
    cudaGetSymbolAddress((void**)&tqkv,    g_tqkv);
    cudaGetSymbolAddress((void**)&attnw,   g_attnw);
    cudaGetSymbolAddress((void**)&tout_bf, g_tout_bf);

    const long long TN = (long long)Tt * NN;      // 16384
    const long long XB = (long long)Cc * TN;      // per-b stride of x/h1/out

    // 0) conversions
    int xN = Bb * Cc * Tt * NN;
    f2b_kernel<<<(xN / 4 + 255) / 256, 256>>>(x, xbf, xN);
    transpose_w_kernel<<<(C3 * Cc + 255) / 256, 256>>>(w_sqkv, wsqkv_t, C3, Cc);
    transpose_w_kernel<<<(Cc * Cc + 255) / 256, 256>>>(w_sout, wsout_t, Cc, Cc);
    transpose_w_kernel<<<(C3 * Cc + 255) / 256, 256>>>(w_tqkv, wtqkv_t, C3, Cc);
    transpose_w_kernel<<<(Cc * Cc + 255) / 256, 256>>>(w_tout, wtout_t, Cc, Cc);

    // 1) spatial qkv -> sqkv fp32 [bt][o][n]
    gemm_bf16<<<dim3(NN / 128, C3 / 128, BT), 256>>>(
        wsqkv_t, xbf, sqkv, nullptr, nullptr, nullptr,
        Cc, C3, Tt,
        XB, NN, TN,
        (long long)Tt * C3 * NN, (long long)C3 * NN, NN);

    // 2-3) softmaxes
    softmax_q<<<dim3(NN / 128, HEADS, BT), 128>>>(sqkv);
    softmax_k<<<dim3(Cc, BT), 256>>>(sqkv);

    // 4) ctx = k v^T
    ctx_kernel<<<dim3(HEADS, BT), 256>>>(sqkv, ctx);

    // 5) out = ctx^T q -> sattn bf16 [bt][c][n]
    attn_apply_kernel<<<dim3(NN / 64, HEADS, BT), 256>>>(sqkv, ctx, sattn_bf);

    // 6) spatial proj + bias -> h1 bf16 [b][o][t][n]
    gemm_bf16<<<dim3(NN / 128, Cc / 128, BT), 256>>>(
        wsout_t, sattn_bf, nullptr, h1_bf, b_sout, nullptr,
        Cc, Cc, Tt,
        (long long)Tt * Cc * NN, (long long)Cc * NN, NN,
        XB, NN, TN);

    // 7) temporal qkv -> tqkv fp32 [b][o][tn]
    gemm_bf16<<<dim3((int)(TN / 128), C3 / 128, Bb), 256>>>(
        wtqkv_t, h1_bf, tqkv, nullptr, nullptr, nullptr,
        Cc, C3, 1,
        XB, 0, TN,
        (long long)C3 * TN, 0, TN);

    // 8-9) temporal attention
    temporal_sim<<<dim3(NN / ST, HEADS, Bb), 128>>>(tqkv, attnw);
    temporal_out<<<dim3(NN / ST, HEADS, Bb), 128>>>(tqkv, attnw, tout_bf);

    // 10) temporal proj + residual -> out fp32
    gemm_bf16<<<dim3((int)(TN / 128), Cc / 128, Bb), 256>>>(
        wtout_t, tout_bf, out, nullptr, nullptr, x,
        Cc, Cc, 1,
        XB, 0, TN,
        XB, 0, TN);
}

// round 3
// speedup vs baseline: 4.6238x; 1.0113x over previous
#include <cuda_runtime.h>
#include <cuda_bf16.h>
#include <math.h>
#include <stdint.h>

#define Bb 2
#define Cc 512
#define Tt 16
#define NN 1024
#define HEADS 8
#define Dd 64
#define BT 32
#define C3 1536

// ---------------- scratch (device globals) ----------------
__device__ __align__(16) __nv_bfloat16 g_wsqkv_t[Cc * C3];
__device__ __align__(16) __nv_bfloat16 g_wsout_t[Cc * Cc];
__device__ __align__(16) __nv_bfloat16 g_wtqkv_t[Cc * C3];
__device__ __align__(16) __nv_bfloat16 g_wtout_t[Cc * Cc];
__device__ __align__(16) __nv_bfloat16 g_xbf[Bb * Cc * Tt * NN];
__device__ __align__(16) float         g_sqkv[BT * C3 * NN];
__device__ __align__(16) float         g_ctx [BT * HEADS * Dd * Dd];
__device__ __align__(16) __nv_bfloat16 g_sattn_bf[BT * Cc * NN];
__device__ __align__(16) __nv_bfloat16 g_h1_bf[Bb * Cc * Tt * NN];
__device__ __align__(16) float         g_tqkv[Bb * C3 * Tt * NN];
__device__ __align__(16) float         g_attnw[Bb * HEADS * Tt * Tt * NN];
__device__ __align__(16) __nv_bfloat16 g_tout_bf[Bb * Cc * Tt * NN];

// ---------------- helpers ----------------
__device__ __forceinline__ uint32_t smem_u32(const void* p) {
    uint32_t a;
    asm("{ .reg .u64 t; cvta.to.shared.u64 t, %1; cvt.u32.u64 %0, t; }" : "=r"(a) : "l"(p));
    return a;
}
#define CP_ASYNC(dst, src) asm volatile("cp.async.cg.shared.global [%0],[%1],16;\n" :: "r"(dst), "l"(src) : "memory")
#define CP_COMMIT()        asm volatile("cp.async.commit_group;\n" ::: "memory")
#define CP_WAIT0()         asm volatile("cp.async.wait_group 0;\n" ::: "memory")

// ---------------- conversions ----------------
__global__ void f2b_kernel(const float* __restrict__ in, __nv_bfloat16* __restrict__ out, int n)
{
    int i = (blockIdx.x * blockDim.x + threadIdx.x) * 4;
    if (i < n) {
        float4 v = *(const float4*)(in + i);
        __nv_bfloat162 p0 = __floats2bfloat162_rn(v.x, v.y);
        __nv_bfloat162 p1 = __floats2bfloat162_rn(v.z, v.w);
        uint2 u;
        u.x = *(uint32_t*)&p0;
        u.y = *(uint32_t*)&p1;
        *(uint2*)(out + i) = u;
    }
}

// W[O][K] fp32 -> Wt[K][O] bf16
__global__ void transpose_w_kernel(const float* __restrict__ in, __nv_bfloat16* __restrict__ out,
                                   int O, int K)
{
    int idx = blockIdx.x * blockDim.x + threadIdx.x;
    if (idx < O * K) {
        int o = idx % O;
        int k = idx / O;
        out[idx] = __float2bfloat16(in[(long long)o * K + k]);
    }
}

// ---------------- bf16 tensor-core GEMM ----------------
// C[g][o][n] = sum_k Wt[k][o] * X[g][k][n]   (both operands k-major in smem)
// BM=128, BN=128, BK=32; 256 threads = 8 warps (2 m x 4 n), warp tile 64x32.
__global__ __launch_bounds__(256, 2) void gemm_bf16(
    const __nv_bfloat16* __restrict__ Wt,   // [K][ldA]
    const __nv_bfloat16* __restrict__ X,
    float* __restrict__ Cf,                 // fp32 out (if Cb == null)
    __nv_bfloat16* __restrict__ Cb,         // bf16 out (if non-null)
    const float* __restrict__ bias,
    const float* __restrict__ res,
    int K, int ldA, int gDiv,
    long long xOuter, long long xInner, long long xRow,
    long long cOuter, long long cInner, long long cRow)
{
    __shared__ __nv_bfloat16 As[2][32][128];
    __shared__ __nv_bfloat16 Bs[2][32][128];

    int g = blockIdx.z;
    long long gq = g / gDiv, gr = g % gDiv;
    const __nv_bfloat16* Xb = X + gq * xOuter + gr * xInner;
    long long cbase = gq * cOuter + gr * cInner;

    int n0 = blockIdx.x * 128;
    int o0 = blockIdx.y * 128;

    int tid = threadIdx.x;
    int lane = tid & 31, warp = tid >> 5;
    int wm = warp >> 2, wn = warp & 3;

    uint32_t asb = smem_u32(&As[0][0][0]);
    uint32_t bsb = smem_u32(&Bs[0][0][0]);

    float acc[4][4][4];
    #pragma unroll
    for (int a = 0; a < 4; a++)
        #pragma unroll
        for (int b = 0; b < 4; b++)
            #pragma unroll
            for (int c = 0; c < 4; c++) acc[a][b][c] = 0.f;

    int nkt = K / 32;

    // issue tile kt into buffer buf
    #define ISSUE_TILE(kt, buf) do {                                                   \
        int k0_ = (kt) * 32;                                                           \
        _Pragma("unroll")                                                              \
        for (int i_ = 0; i_ < 2; i_++) {                                               \
            int idx_ = tid + 256 * i_;                                                 \
            int row_ = idx_ >> 4, ch_ = idx_ & 15;                                     \
            const __nv_bfloat16* sA = Wt + (long long)(k0_ + row_) * ldA + o0 + ch_ * 8; \
            uint32_t dA = asb + (buf) * 8192 + row_ * 256 + (((ch_) ^ (row_ & 7)) << 4); \
            CP_ASYNC(dA, sA);                                                          \
            const __nv_bfloat16* sB = Xb + (long long)(k0_ + row_) * xRow + n0 + ch_ * 8; \
            uint32_t dB = bsb + (buf) * 8192 + row_ * 256 + (((ch_) ^ (row_ & 7)) << 4); \
            CP_ASYNC(dB, sB);                                                          \
        }                                                                              \
    } while (0)

    ISSUE_TILE(0, 0);
    CP_COMMIT();

    int r7 = lane & 7, sub = lane >> 3;
    int brow_lo = lane & 15;

    for (int kt = 0; kt < nkt; kt++) {
        CP_WAIT0();
        __syncthreads();
        if (kt + 1 < nkt) {
            ISSUE_TILE(kt + 1, (kt + 1) & 1);
            CP_COMMIT();
        }
        int buf = kt & 1;
        uint32_t abase = asb + buf * 8192;
        uint32_t bbase = bsb + buf * 8192;

        #pragma unroll
        for (int ks = 0; ks < 2; ks++) {
            uint32_t af[4][4];
            uint32_t bf_[4][2];
            #pragma unroll
            for (int mt = 0; mt < 4; mt++) {
                int krow = ks * 16 + r7 + ((sub >> 1) << 3);
                int mcol = wm * 64 + mt * 16 + ((sub & 1) << 3);
                uint32_t addr = abase + krow * 256 + ((((mcol >> 3)) ^ (krow & 7)) << 4);
                asm volatile("ldmatrix.sync.aligned.m8n8.x4.trans.shared.b16 {%0,%1,%2,%3},[%4];"
                             : "=r"(af[mt][0]), "=r"(af[mt][1]), "=r"(af[mt][2]), "=r"(af[mt][3])
                             : "r"(addr));
            }
            #pragma unroll
            for (int nt = 0; nt < 4; nt++) {
                int brow = ks * 16 + brow_lo;
                int ncol = wn * 32 + nt * 8;
                uint32_t addr = bbase + brow * 256 + ((((ncol >> 3)) ^ (brow & 7)) << 4);
                asm volatile("ldmatrix.sync.aligned.m8n8.x2.trans.shared.b16 {%0,%1},[%2];"
                             : "=r"(bf_[nt][0]), "=r"(bf_[nt][1])
                             : "r"(addr));
            }
            #pragma unroll
            for (int mt = 0; mt < 4; mt++)
                #pragma unroll
                for (int nt = 0; nt < 4; nt++) {
                    asm volatile(
                        "mma.sync.aligned.m16n8k16.row.col.f32.bf16.bf16.f32 "
                        "{%0,%1,%2,%3},{%4,%5,%6,%7},{%8,%9},{%0,%1,%2,%3};"
                        : "+f"(acc[mt][nt][0]), "+f"(acc[mt][nt][1]),
                          "+f"(acc[mt][nt][2]), "+f"(acc[mt][nt][3])
                        : "r"(af[mt][0]), "r"(af[mt][1]), "r"(af[mt][2]), "r"(af[mt][3]),
                          "r"(bf_[nt][0]), "r"(bf_[nt][1]));
                }
        }
    }

    // epilogue
    int g4 = lane >> 2, t4 = lane & 3;
    #pragma unroll
    for (int mt = 0; mt < 4; mt++) {
        #pragma unroll
        for (int nt = 0; nt < 4; nt++) {
            int orow = o0 + wm * 64 + mt * 16 + g4;
            int col  = n0 + wn * 32 + nt * 8 + t4 * 2;
            long long off0 = cbase + (long long)orow * cRow + col;
            long long off1 = off0 + 8 * cRow;
            float b0 = bias ? bias[orow] : 0.f;
            float b1 = bias ? bias[orow + 8] : 0.f;
            float* a = acc[mt][nt];
            if (Cb) {
                __nv_bfloat162 v0 = __floats2bfloat162_rn(a[0] + b0, a[1] + b0);
                __nv_bfloat162 v1 = __floats2bfloat162_rn(a[2] + b1, a[3] + b1);
                *reinterpret_cast<__nv_bfloat162*>(Cb + off0) = v0;
                *reinterpret_cast<__nv_bfloat162*>(Cb + off1) = v1;
            } else {
                float2 r0 = make_float2(0.f, 0.f), r1 = make_float2(0.f, 0.f);
                if (res) { r0 = *(const float2*)(res + off0); r1 = *(const float2*)(res + off1); }
                float2 o0v = make_float2(a[0] + b0 + r0.x, a[1] + b0 + r0.y);
                float2 o1v = make_float2(a[2] + b1 + r1.x, a[3] + b1 + r1.y);
                *(float2*)(Cf + off0) = o0v;
                *(float2*)(Cf + off1) = o1v;
            }
        }
    }
    #undef ISSUE_TILE
}

// ---------------- spatial softmaxes ----------------
__global__ void softmax_q(float* __restrict__ p)
{
    int n = blockIdx.x * 128 + threadIdx.x;
    long long base = (long long)blockIdx.z * C3 * NN + (long long)blockIdx.y * Dd * NN + n;
    float m = p[base];
    float s = 1.f;
    for (int d = 1; d < Dd; d++) {
        float v = p[base + (long long)d * NN];
        float nm = fmaxf(m, v);
        s = s * __expf(m - nm) + __expf(v - nm);
        m = nm;
    }
    float inv = 0.125f / s;
    for (int d = 0; d < Dd; d++) {
        long long idx = base + (long long)d * NN;
        p[idx] = __expf(p[idx] - m) * inv;
    }
}

__global__ __launch_bounds__(256) void softmax_k(float* __restrict__ p)
{
    float* row = p + (long long)blockIdx.y * C3 * NN + (long long)(Cc + blockIdx.x) * NN;
    int tid = threadIdx.x;
    float v[4];
    float m = -INFINITY;
    #pragma unroll
    for (int k = 0; k < 4; k++) { v[k] = row[tid + 256 * k]; m = fmaxf(m, v[k]); }
    __shared__ float red[8];
    #pragma unroll
    for (int o = 16; o; o >>= 1) m = fmaxf(m, __shfl_xor_sync(0xffffffffu, m, o));
    if ((tid & 31) == 0) red[tid >> 5] = m;
    __syncthreads();
    m = red[0];
    #pragma unroll
    for (int wv = 1; wv < 8; wv++) m = fmaxf(m, red[wv]);
    __syncthreads();
    float s = 0.f;
    #pragma unroll
    for (int k = 0; k < 4; k++) { v[k] = __expf(v[k] - m); s += v[k]; }
    #pragma unroll
    for (int o = 16; o; o >>= 1) s += __shfl_xor_sync(0xffffffffu, s, o);
    if ((tid & 31) == 0) red[tid >> 5] = s;
    __syncthreads();
    s = 0.f;
    #pragma unroll
    for (int wv = 0; wv < 8; wv++) s += red[wv];
    float inv = 1.f / s;
    #pragma unroll
    for (int k = 0; k < 4; k++) row[tid + 256 * k] = v[k] * inv;
}

// ---------------- spatial: ctx[d][e] = sum_n k[d][n] * v[e][n] ----------------
__global__ __launch_bounds__(256) void ctx_kernel(const float* __restrict__ qkv,
                                                  float* __restrict__ ctx)
{
    int h = blockIdx.x, bt = blockIdx.y;
    const float* kbase = qkv + (long long)bt * C3 * NN + (long long)(Cc + h * Dd) * NN;
    const float* vbase = qkv + (long long)bt * C3 * NN + (long long)(2 * Cc + h * Dd) * NN;
    __shared__ float Ks[64][68];
    __shared__ float Vs[64][68];
    int tid = threadIdx.x;
    int tx = tid & 15, ty = tid >> 4;
    float acc[4][4] = {};
    for (int n0 = 0; n0 < NN; n0 += 64) {
        #pragma unroll
        for (int l = 0; l < 16; l++) {
            int idx = l * 256 + tid;
            int d = idx >> 6, nn = idx & 63;
            Ks[nn][d] = kbase[(long long)d * NN + n0 + nn];
            Vs[nn][d] = vbase[(long long)d * NN + n0 + nn];
        }
        __syncthreads();
        #pragma unroll
        for (int nn = 0; nn < 64; nn++) {
            float4 a = *(float4*)&Ks[nn][ty * 4];
            float4 b = *(float4*)&Vs[nn][tx * 4];
            float aa[4] = {a.x, a.y, a.z, a.w};
            float bb[4] = {b.x, b.y, b.z, b.w};
            #pragma unroll
            for (int i = 0; i < 4; i++)
                #pragma unroll
                for (int j = 0; j < 4; j++)
                    acc[i][j] += aa[i] * bb[j];
        }
        __syncthreads();
    }
    float* cb = ctx + ((long long)bt * HEADS + h) * Dd * Dd;
    #pragma unroll
    for (int i = 0; i < 4; i++) {
        float4 ov = make_float4(acc[i][0], acc[i][1], acc[i][2], acc[i][3]);
        *(float4*)&cb[(ty * 4 + i) * Dd + tx * 4] = ov;
    }
}

// ---------------- spatial: out[e][n] = sum_d ctx[d][e] * q[d][n]  (bf16 out) ----------------
__global__ __launch_bounds__(256) void attn_apply_kernel(const float* __restrict__ qkv,
                                                         const float* __restrict__ ctx,
                                                         __nv_bfloat16* __restrict__ out)
{
    int n0 = blockIdx.x * 64, h = blockIdx.y, bt = blockIdx.z;
    const float* qbase = qkv + (long long)bt * C3 * NN + (long long)(h * Dd) * NN;
    const float* cb = ctx + ((long long)bt * HEADS + h) * Dd * Dd;
    __shared__ float As[64][68];
    __shared__ float Bs[64][68];
    int tid = threadIdx.x;
    int tx = tid & 15, ty = tid >> 4;
    #pragma unroll
    for (int l = 0; l < 16; l++) {
        int idx = l * 256 + tid;
        int d = idx >> 6, e = idx & 63;
        As[d][e] = cb[idx];
        Bs[d][e] = qbase[(long long)d * NN + n0 + e];
    }
    __syncthreads();
    float acc[4][4] = {};
    #pragma unroll
    for (int d = 0; d < 64; d++) {
        float4 a = *(float4*)&As[d][ty * 4];
        float4 b = *(float4*)&Bs[d][tx * 4];
        float aa[4] = {a.x, a.y, a.z, a.w};
        float bb[4] = {b.x, b.y, b.z, b.w};
        #pragma unroll
        for (int i = 0; i < 4; i++)
            #pragma unroll
            for (int j = 0; j < 4; j++)
                acc[i][j] += aa[i] * bb[j];
    }
    __nv_bfloat16* ob = out + (long long)bt * Cc * NN + (long long)(h * Dd) * NN;
    #pragma unroll
    for (int i = 0; i < 4; i++) {
        __nv_bfloat162 p0 = __floats2bfloat162_rn(acc[i][0], acc[i][1]);
        __nv_bfloat162 p1 = __floats2bfloat162_rn(acc[i][2], acc[i][3]);
        long long off = (long long)(ty * 4 + i) * NN + n0 + tx * 4;
        *reinterpret_cast<__nv_bfloat162*>(ob + off) = p0;
        *reinterpret_cast<__nv_bfloat162*>(ob + off + 2) = p1;
    }
}

// ---------------- temporal attention ----------------
#define ST 8
__global__ __launch_bounds__(128) void temporal_sim(const float* __restrict__ tqkv,
                                                    float* __restrict__ attn)
{
    int b = blockIdx.z, hh = blockIdx.y;
    int s0 = blockIdx.x * ST;
    __shared__ float ks[16 * 64 * (ST + 1)];
    const float* kb = tqkv + ((long long)b * C3 + Cc + hh * Dd) * (Tt * NN);
    int tid = threadIdx.x;
    #pragma unroll
    for (int l = 0; l < (16 * 64 * ST) / 128; l++) {
        int idx = l * 128 + tid;
        int s = idx & (ST - 1);
        int rest = idx >> 3;
        int d = rest & 63, j = rest >> 6;
        ks[rest * (ST + 1) + s] = kb[(long long)d * (Tt * NN) + j * NN + s0 + s];
    }
    __syncthreads();
    int sl = tid & (ST - 1);
    int i  = tid >> 3;
    const float* qb = tqkv + ((long long)b * C3 + hh * Dd) * (Tt * NN) + (long long)i * NN + s0 + sl;
    float acc[16];
    #pragma unroll
    for (int j = 0; j < 16; j++) acc[j] = 0.f;
    for (int d = 0; d < 64; d++) {
        float qv = qb[(long long)d * (Tt * NN)] * 0.125f;
        #pragma unroll
        for (int j = 0; j < 16; j++)
            acc[j] += qv * ks[(j * 64 + d) * (ST + 1) + sl];
    }
    float m = acc[0];
    #pragma unroll
    for (int j = 1; j < 16; j++) m = fmaxf(m, acc[j]);
    float sum = 0.f;
    #pragma unroll
    for (int j = 0; j < 16; j++) { acc[j] = __expf(acc[j] - m); sum += acc[j]; }
    float inv = 1.f / sum;
    float* ab = attn + (((long long)b * HEADS + hh) * Tt + i) * Tt * NN + s0 + sl;
    #pragma unroll
    for (int j = 0; j < 16; j++)
        ab[(long long)j * NN] = acc[j] * inv;
}

__global__ __launch_bounds__(128) void temporal_out(const float* __restrict__ tqkv,
                                                    const float* __restrict__ attn,
                                                    __nv_bfloat16* __restrict__ out)
{
    int b = blockIdx.z, hh = blockIdx.y;
    int s0 = blockIdx.x * ST;
    __shared__ float vs[16 * 64 * (ST + 1)];
    const float* vb = tqkv + ((long long)b * C3 + 2 * Cc + hh * Dd) * (Tt * NN);
    int tid = threadIdx.x;
    #pragma unroll
    for (int l = 0; l < (16 * 64 * ST) / 128; l++) {
        int idx = l * 128 + tid;
        int s = idx & (ST - 1);
        int rest = idx >> 3;
        int d = rest & 63, j = rest >> 6;
        vs[rest * (ST + 1) + s] = vb[(long long)d * (Tt * NN) + j * NN + s0 + s];
    }
    __syncthreads();
    int sl = tid & (ST - 1);
    int dg = tid >> 3;
    const float* ab = attn + ((long long)b * HEADS + hh) * (Tt * Tt) * NN + s0 + sl;
    __nv_bfloat16* ob = out + ((long long)b * Cc + hh * Dd + dg * 4) * (Tt * NN) + s0 + sl;
    for (int i = 0; i < 16; i++) {
        float a0 = 0.f, a1 = 0.f, a2 = 0.f, a3 = 0.f;
        #pragma unroll
        for (int j = 0; j < 16; j++) {
            float av = ab[(long long)(i * 16 + j) * NN];
            a0 += av * vs[(j * 64 + dg * 4 + 0) * (ST + 1) + sl];
            a1 += av * vs[(j * 64 + dg * 4 + 1) * (ST + 1) + sl];
            a2 += av * vs[(j * 64 + dg * 4 + 2) * (ST + 1) + sl];
            a3 += av * vs[(j * 64 + dg * 4 + 3) * (ST + 1) + sl];
        }
        long long t_off = (long long)i * NN;
        ob[t_off + 0 * (long long)(Tt * NN)] = __float2bfloat16(a0);
        ob[t_off + 1 * (long long)(Tt * NN)] = __float2bfloat16(a1);
        ob[t_off + 2 * (long long)(Tt * NN)] = __float2bfloat16(a2);
        ob[t_off + 3 * (long long)(Tt * NN)] = __float2bfloat16(a3);
    }
}

// ---------------- launch ----------------
extern "C" void kernel_launch(void* const* d_in, const int* in_sizes, int n_in,
                              void* d_out, int out_size)
{
    const float* x      = (const float*)d_in[0];
    const float* w_sqkv = (const float*)d_in[1];
    const float* w_sout = (const float*)d_in[2];
    const float* b_sout = (const float*)d_in[3];
    const float* w_tqkv = (const float*)d_in[4];
    const float* w_tout = (const float*)d_in[5];
    float* out = (float*)d_out;

    __nv_bfloat16 *wsqkv_t, *wsout_t, *wtqkv_t, *wtout_t, *xbf, *sattn_bf, *h1_bf, *tout_bf;
    float *sqkv, *ctx, *tqkv, *attnw;
    cudaGetSymbolAddress((void**)&wsqkv_t, g_wsqkv_t);
    cudaGetSymbolAddress((void**)&wsout_t, g_wsout_t);
    cudaGetSymbolAddress((void**)&wtqkv_t, g_wtqkv_t);
    cudaGetSymbolAddress((void**)&wtout_t, g_wtout_t);
    cudaGetSymbolAddress((void**)&xbf,     g_xbf);
    cudaGetSymbolAddress((void**)&sqkv,    g_sqkv);
    cudaGetSymbolAddress((void**)&ctx,     g_ctx);
    cudaGetSymbolAddress((void**)&sattn_bf,g_sattn_bf);
    cudaGetSymbolAddress((void**)&h1_bf,   g_h1_bf);
    cudaGetSymbolAddress((void**)&tqkv,    g_tqkv);
    cudaGetSymbolAddress((void**)&attnw,   g_attnw);
    cudaGetSymbolAddress((void**)&tout_bf, g_tout_bf);

    const long long TN = (long long)Tt * NN;      // 16384
    const long long XB = (long long)Cc * TN;      // per-b stride of x/h1/out

    // 0) conversions
    int xN = Bb * Cc * Tt * NN;
    f2b_kernel<<<(xN / 4 + 255) / 256, 256>>>(x, xbf, xN);
    transpose_w_kernel<<<(C3 * Cc + 255) / 256, 256>>>(w_sqkv, wsqkv_t, C3, Cc);
    transpose_w_kernel<<<(Cc * Cc + 255) / 256, 256>>>(w_sout, wsout_t, Cc, Cc);
    transpose_w_kernel<<<(C3 * Cc + 255) / 256, 256>>>(w_tqkv, wtqkv_t, C3, Cc);
    transpose_w_kernel<<<(Cc * Cc + 255) / 256, 256>>>(w_tout, wtout_t, Cc, Cc);

    // 1) spatial qkv -> sqkv fp32 [bt][o][n]
    gemm_bf16<<<dim3(NN / 128, C3 / 128, BT), 256>>>(
        wsqkv_t, xbf, sqkv, nullptr, nullptr, nullptr,
        Cc, C3, Tt,
        XB, NN, TN,
        (long long)Tt * C3 * NN, (long long)C3 * NN, NN);

    // 2-3) softmaxes
    softmax_q<<<dim3(NN / 128, HEADS, BT), 128>>>(sqkv);
    softmax_k<<<dim3(Cc, BT), 256>>>(sqkv);

    // 4) ctx = k v^T
    ctx_kernel<<<dim3(HEADS, BT), 256>>>(sqkv, ctx);

    // 5) out = ctx^T q -> sattn bf16 [bt][c][n]
    attn_apply_kernel<<<dim3(NN / 64, HEADS, BT), 256>>>(sqkv, ctx, sattn_bf);

    // 6) spatial proj + bias -> h1 bf16 [b][o][t][n]
    gemm_bf16<<<dim3(NN / 128, Cc / 128, BT), 256>>>(
        wsout_t, sattn_bf, nullptr, h1_bf, b_sout, nullptr,
        Cc, Cc, Tt,
        (long long)Tt * Cc * NN, (long long)Cc * NN, NN,
        XB, NN, TN);

    // 7) temporal qkv -> tqkv fp32 [b][o][tn]
    gemm_bf16<<<dim3((int)(TN / 128), C3 / 128, Bb), 256>>>(
        wtqkv_t, h1_bf, tqkv, nullptr, nullptr, nullptr,
        Cc, C3, 1,
        XB, 0, TN,
        (long long)C3 * TN, 0, TN);

    // 8-9) temporal attention
    temporal_sim<<<dim3(NN / ST, HEADS, Bb), 128>>>(tqkv, attnw);
    temporal_out<<<dim3(NN / ST, HEADS, Bb), 128>>>(tqkv, attnw, tout_bf);

    // 10) temporal proj + residual -> out fp32
    gemm_bf16<<<dim3((int)(TN / 128), Cc / 128, Bb), 256>>>(
        wtout_t, tout_bf, out, nullptr, nullptr, x,
        Cc, Cc, 1,
        XB, 0, TN,
        XB, 0, TN);
}

// round 4
// speedup vs baseline: 5.5169x; 1.1932x over previous
#include <cuda_runtime.h>
#include <cuda_bf16.h>
#include <math.h>
#include <stdint.h>

#define Bb 2
#define Cc 512
#define Tt 16
#define NN 1024
#define HEADS 8
#define Dd 64
#define BT 32
#define C3 1536

typedef __nv_bfloat16 bf16;

// ---------------- scratch (device globals) ----------------
__device__ __align__(16) bf16  g_wsqkv_t[Cc * C3];
__device__ __align__(16) bf16  g_wsout_t[Cc * Cc];
__device__ __align__(16) bf16  g_wtqkv_t[Cc * C3];
__device__ __align__(16) bf16  g_wtout_t[Cc * Cc];
__device__ __align__(16) bf16  g_xbf[Bb * Cc * Tt * NN];
__device__ __align__(16) bf16  g_sqkv[BT * C3 * NN];            // bf16 now
__device__ __align__(16) bf16  g_ctx_ed[BT * HEADS * Dd * Dd];  // ctx transposed [e][d], bf16
__device__ __align__(16) bf16  g_sattn_bf[BT * Cc * NN];
__device__ __align__(16) bf16  g_h1_bf[Bb * Cc * Tt * NN];
__device__ __align__(16) bf16  g_tqkv[Bb * C3 * Tt * NN];       // bf16 now
__device__ __align__(16) float g_attnw[Bb * HEADS * Tt * Tt * NN];
__device__ __align__(16) bf16  g_tout_bf[Bb * Cc * Tt * NN];

// ---------------- helpers ----------------
__device__ __forceinline__ uint32_t smem_u32(const void* p) {
    uint32_t a;
    asm("{ .reg .u64 t; cvta.to.shared.u64 t, %1; cvt.u32.u64 %0, t; }" : "=r"(a) : "l"(p));
    return a;
}
#define CP_ASYNC(dst, src) asm volatile("cp.async.cg.shared.global [%0],[%1],16;\n" :: "r"(dst), "l"(src) : "memory")
#define CP_COMMIT()        asm volatile("cp.async.commit_group;\n" ::: "memory")
#define CP_WAIT0()         asm volatile("cp.async.wait_group 0;\n" ::: "memory")
#define CP_WAIT1()         asm volatile("cp.async.wait_group 1;\n" ::: "memory")

#define LDSM_X4(r0,r1,r2,r3,addr) \
    asm volatile("ldmatrix.sync.aligned.m8n8.x4.shared.b16 {%0,%1,%2,%3},[%4];" \
                 : "=r"(r0),"=r"(r1),"=r"(r2),"=r"(r3) : "r"(addr))
#define LDSM_X4T(r0,r1,r2,r3,addr) \
    asm volatile("ldmatrix.sync.aligned.m8n8.x4.trans.shared.b16 {%0,%1,%2,%3},[%4];" \
                 : "=r"(r0),"=r"(r1),"=r"(r2),"=r"(r3) : "r"(addr))
#define LDSM_X2T(r0,r1,addr) \
    asm volatile("ldmatrix.sync.aligned.m8n8.x2.trans.shared.b16 {%0,%1},[%2];" \
                 : "=r"(r0),"=r"(r1) : "r"(addr))
#define MMA16816(d0,d1,d2,d3,a0,a1,a2,a3,b0,b1) \
    asm volatile("mma.sync.aligned.m16n8k16.row.col.f32.bf16.bf16.f32 " \
                 "{%0,%1,%2,%3},{%4,%5,%6,%7},{%8,%9},{%0,%1,%2,%3};" \
                 : "+f"(d0),"+f"(d1),"+f"(d2),"+f"(d3) \
                 : "r"(a0),"r"(a1),"r"(a2),"r"(a3),"r"(b0),"r"(b1))

// ---------------- conversions ----------------
__global__ void f2b_kernel(const float* __restrict__ in, bf16* __restrict__ out, int n)
{
    int i = (blockIdx.x * blockDim.x + threadIdx.x) * 4;
    if (i < n) {
        float4 v = *(const float4*)(in + i);
        __nv_bfloat162 p0 = __floats2bfloat162_rn(v.x, v.y);
        __nv_bfloat162 p1 = __floats2bfloat162_rn(v.z, v.w);
        uint2 u;
        u.x = *(uint32_t*)&p0;
        u.y = *(uint32_t*)&p1;
        *(uint2*)(out + i) = u;
    }
}

__global__ void transpose_w_kernel(const float* __restrict__ in, bf16* __restrict__ out,
                                   int O, int K)
{
    int idx = blockIdx.x * blockDim.x + threadIdx.x;
    if (idx < O * K) {
        int o = idx % O;
        int k = idx / O;
        out[idx] = __float2bfloat16(in[(long long)o * K + k]);
    }
}

// ---------------- main bf16 tensor-core GEMM (3-stage pipeline) ----------------
__global__ __launch_bounds__(256, 2) void gemm_bf16(
    const bf16* __restrict__ Wt,   // [K][ldA]
    const bf16* __restrict__ X,
    float* __restrict__ Cf,
    bf16* __restrict__ Cb,
    const float* __restrict__ bias,
    const float* __restrict__ res,
    int K, int ldA, int gDiv,
    long long xOuter, long long xInner, long long xRow,
    long long cOuter, long long cInner, long long cRow)
{
    __shared__ bf16 As[3][32][128];
    __shared__ bf16 Bs[3][32][128];

    int g = blockIdx.z;
    long long gq = g / gDiv, gr = g % gDiv;
    const bf16* Xb = X + gq * xOuter + gr * xInner;
    long long cbase = gq * cOuter + gr * cInner;

    int n0 = blockIdx.x * 128;
    int o0 = blockIdx.y * 128;

    int tid = threadIdx.x;
    int lane = tid & 31, warp = tid >> 5;
    int wm = warp >> 2, wn = warp & 3;

    uint32_t asb = smem_u32(&As[0][0][0]);
    uint32_t bsb = smem_u32(&Bs[0][0][0]);

    float acc[4][4][4];
    #pragma unroll
    for (int a = 0; a < 4; a++)
        #pragma unroll
        for (int b = 0; b < 4; b++)
            #pragma unroll
            for (int c = 0; c < 4; c++) acc[a][b][c] = 0.f;

    int nkt = K / 32;

    #define ISSUE_TILE(kt, buf) do {                                                     \
        int k0_ = (kt) * 32;                                                             \
        _Pragma("unroll")                                                                \
        for (int i_ = 0; i_ < 2; i_++) {                                                 \
            int idx_ = tid + 256 * i_;                                                   \
            int row_ = idx_ >> 4, ch_ = idx_ & 15;                                       \
            const bf16* sA = Wt + (long long)(k0_ + row_) * ldA + o0 + ch_ * 8;          \
            uint32_t dA = asb + (buf) * 8192 + row_ * 256 + (((ch_) ^ (row_ & 7)) << 4); \
            CP_ASYNC(dA, sA);                                                            \
            const bf16* sB = Xb + (long long)(k0_ + row_) * xRow + n0 + ch_ * 8;         \
            uint32_t dB = bsb + (buf) * 8192 + row_ * 256 + (((ch_) ^ (row_ & 7)) << 4); \
            CP_ASYNC(dB, sB);                                                            \
        }                                                                                \
    } while (0)

    ISSUE_TILE(0, 0);
    CP_COMMIT();
    ISSUE_TILE(1, 1);
    CP_COMMIT();

    int r7 = lane & 7, sub = lane >> 3;
    int brow_lo = lane & 15;

    for (int kt = 0; kt < nkt; kt++) {
        CP_WAIT1();
        __syncthreads();
        if (kt + 2 < nkt) {
            int nb = (kt + 2) % 3;
            ISSUE_TILE(kt + 2, nb);
        }
        CP_COMMIT();
        int buf = kt % 3;
        uint32_t abase = asb + buf * 8192;
        uint32_t bbase = bsb + buf * 8192;

        #pragma unroll
        for (int ks = 0; ks < 2; ks++) {
            uint32_t af[4][4];
            uint32_t bf_[4][2];
            #pragma unroll
            for (int mt = 0; mt < 4; mt++) {
                int krow = ks * 16 + r7 + ((sub >> 1) << 3);
                int mcol = wm * 64 + mt * 16 + ((sub & 1) << 3);
                uint32_t addr = abase + krow * 256 + ((((mcol >> 3)) ^ (krow & 7)) << 4);
                LDSM_X4T(af[mt][0], af[mt][1], af[mt][2], af[mt][3], addr);
            }
            #pragma unroll
            for (int nt = 0; nt < 4; nt++) {
                int brow = ks * 16 + brow_lo;
                int ncol = wn * 32 + nt * 8;
                uint32_t addr = bbase + brow * 256 + ((((ncol >> 3)) ^ (brow & 7)) << 4);
                LDSM_X2T(bf_[nt][0], bf_[nt][1], addr);
            }
            #pragma unroll
            for (int mt = 0; mt < 4; mt++)
                #pragma unroll
                for (int nt = 0; nt < 4; nt++)
                    MMA16816(acc[mt][nt][0], acc[mt][nt][1], acc[mt][nt][2], acc[mt][nt][3],
                             af[mt][0], af[mt][1], af[mt][2], af[mt][3],
                             bf_[nt][0], bf_[nt][1]);
        }
    }

    int g4 = lane >> 2, t4 = lane & 3;
    #pragma unroll
    for (int mt = 0; mt < 4; mt++) {
        #pragma unroll
        for (int nt = 0; nt < 4; nt++) {
            int orow = o0 + wm * 64 + mt * 16 + g4;
            int col  = n0 + wn * 32 + nt * 8 + t4 * 2;
            long long off0 = cbase + (long long)orow * cRow + col;
            long long off1 = off0 + 8 * cRow;
            float b0 = bias ? bias[orow] : 0.f;
            float b1 = bias ? bias[orow + 8] : 0.f;
            float* a = acc[mt][nt];
            if (Cb) {
                __nv_bfloat162 v0 = __floats2bfloat162_rn(a[0] + b0, a[1] + b0);
                __nv_bfloat162 v1 = __floats2bfloat162_rn(a[2] + b1, a[3] + b1);
                *reinterpret_cast<__nv_bfloat162*>(Cb + off0) = v0;
                *reinterpret_cast<__nv_bfloat162*>(Cb + off1) = v1;
            } else {
                float2 r0 = make_float2(0.f, 0.f), r1 = make_float2(0.f, 0.f);
                if (res) { r0 = *(const float2*)(res + off0); r1 = *(const float2*)(res + off1); }
                float2 o0v = make_float2(a[0] + b0 + r0.x, a[1] + b0 + r0.y);
                float2 o1v = make_float2(a[2] + b1 + r1.x, a[3] + b1 + r1.y);
                *(float2*)(Cf + off0) = o0v;
                *(float2*)(Cf + off1) = o1v;
            }
        }
    }
    #undef ISSUE_TILE
}

// ---------------- spatial softmaxes (bf16 in/out, fp32 math) ----------------
__global__ __launch_bounds__(128) void softmax_q(bf16* __restrict__ p)
{
    int n = blockIdx.x * 128 + threadIdx.x;
    long long base = (long long)blockIdx.z * C3 * NN + (long long)blockIdx.y * Dd * NN + n;
    float v[Dd];
    #pragma unroll
    for (int d = 0; d < Dd; d++) v[d] = __bfloat162float(p[base + (long long)d * NN]);
    float m = v[0];
    #pragma unroll
    for (int d = 1; d < Dd; d++) m = fmaxf(m, v[d]);
    float s = 0.f;
    #pragma unroll
    for (int d = 0; d < Dd; d++) { v[d] = __expf(v[d] - m); s += v[d]; }
    float inv = 0.125f / s;
    #pragma unroll
    for (int d = 0; d < Dd; d++)
        p[base + (long long)d * NN] = __float2bfloat16(v[d] * inv);
}

__global__ __launch_bounds__(256) void softmax_k(bf16* __restrict__ p)
{
    bf16* row = p + (long long)blockIdx.y * C3 * NN + (long long)(Cc + blockIdx.x) * NN;
    int tid = threadIdx.x;
    float v[4];
    float m = -INFINITY;
    #pragma unroll
    for (int k = 0; k < 4; k++) { v[k] = __bfloat162float(row[tid + 256 * k]); m = fmaxf(m, v[k]); }
    __shared__ float red[8];
    #pragma unroll
    for (int o = 16; o; o >>= 1) m = fmaxf(m, __shfl_xor_sync(0xffffffffu, m, o));
    if ((tid & 31) == 0) red[tid >> 5] = m;
    __syncthreads();
    m = red[0];
    #pragma unroll
    for (int wv = 1; wv < 8; wv++) m = fmaxf(m, red[wv]);
    __syncthreads();
    float s = 0.f;
    #pragma unroll
    for (int k = 0; k < 4; k++) { v[k] = __expf(v[k] - m); s += v[k]; }
    #pragma unroll
    for (int o = 16; o; o >>= 1) s += __shfl_xor_sync(0xffffffffu, s, o);
    if ((tid & 31) == 0) red[tid >> 5] = s;
    __syncthreads();
    s = 0.f;
    #pragma unroll
    for (int wv = 0; wv < 8; wv++) s += red[wv];
    float inv = 1.f / s;
    #pragma unroll
    for (int k = 0; k < 4; k++) row[tid + 256 * k] = __float2bfloat16(v[k] * inv);
}

// ---------------- ctx (tensor core): ctx_ed[e][d] = sum_n k[d][n] v[e][n] ----------------
// per (bt,h): M=64 (d), N=64 (e), K=1024 (n). A=K[d][n] row-major, B=V[e][n] n-contig.
__global__ __launch_bounds__(128) void ctx_mma(const bf16* __restrict__ qkv,
                                               bf16* __restrict__ ctx_ed)
{
    int h = blockIdx.x, bt = blockIdx.y;
    const bf16* kbase = qkv + (long long)bt * C3 * NN + (long long)(Cc + h * Dd) * NN;
    const bf16* vbase = qkv + (long long)bt * C3 * NN + (long long)(2 * Cc + h * Dd) * NN;

    __shared__ bf16 Ks[2][64 * 64];
    __shared__ bf16 Vs[2][64 * 64];
    uint32_t ksb = smem_u32(&Ks[0][0]);
    uint32_t vsb = smem_u32(&Vs[0][0]);

    int tid = threadIdx.x;
    int lane = tid & 31, warp = tid >> 5;
    int m0 = warp * 16;

    float acc[8][4] = {};

    #define CTX_ISSUE(c, buf) do {                                                  \
        _Pragma("unroll")                                                           \
        for (int i_ = 0; i_ < 8; i_++) {                                            \
            int idx_ = i_ * 128 + tid;                                              \
            int mat_ = idx_ >> 9;                                                   \
            int rem_ = idx_ & 511;                                                  \
            int row_ = rem_ >> 3, ch_ = rem_ & 7;                                   \
            const bf16* src_ = (mat_ ? vbase : kbase) + (long long)row_ * NN + (c) * 64 + ch_ * 8; \
            uint32_t dst_ = (mat_ ? vsb : ksb) + (buf) * 8192 + row_ * 128 + ((ch_ ^ (row_ & 7)) << 4); \
            CP_ASYNC(dst_, src_);                                                   \
        }                                                                           \
    } while (0)

    CTX_ISSUE(0, 0);
    CP_COMMIT();

    for (int c = 0; c < 16; c++) {
        CP_WAIT0();
        __syncthreads();
        if (c + 1 < 16) { CTX_ISSUE(c + 1, (c + 1) & 1); CP_COMMIT(); }
        int buf = c & 1;
        uint32_t ka = ksb + buf * 8192;
        uint32_t va = vsb + buf * 8192;
        #pragma unroll
        for (int ks = 0; ks < 4; ks++) {
            int k0 = ks * 16;
            // A fragment (non-trans): rows m0+(lane&15), chunk k0/8 + (lane>>4)
            uint32_t a0, a1, a2, a3;
            {
                int row = m0 + (lane & 15);
                int ch  = (k0 >> 3) + (lane >> 4);
                uint32_t addr = ka + row * 128 + ((ch ^ (row & 7)) << 4);
                LDSM_X4(a0, a1, a2, a3, addr);
            }
            // B fragments: 4 x4 loads covering n=64
            #pragma unroll
            for (int nb = 0; nb < 4; nb++) {
                int row = nb * 16 + ((lane >> 4) << 3) + (lane & 7);
                int ch  = (k0 >> 3) + ((lane >> 3) & 1);
                uint32_t addr = va + row * 128 + ((ch ^ (row & 7)) << 4);
                uint32_t r0, r1, r2, r3;
                LDSM_X4(r0, r1, r2, r3, addr);
                MMA16816(acc[nb*2][0],   acc[nb*2][1],   acc[nb*2][2],   acc[nb*2][3],
                         a0, a1, a2, a3, r0, r1);
                MMA16816(acc[nb*2+1][0], acc[nb*2+1][1], acc[nb*2+1][2], acc[nb*2+1][3],
                         a0, a1, a2, a3, r2, r3);
            }
        }
    }
    #undef CTX_ISSUE

    // write transposed [e][d] bf16
    bf16* cb = ctx_ed + ((long long)bt * HEADS + h) * (Dd * Dd);
    int g4 = lane >> 2, t4 = lane & 3;
    #pragma unroll
    for (int nt = 0; nt < 8; nt++) {
        int e0 = nt * 8 + t4 * 2;
        int d0 = m0 + g4;
        cb[(e0)     * Dd + d0]     = __float2bfloat16(acc[nt][0]);
        cb[(e0 + 1) * Dd + d0]     = __float2bfloat16(acc[nt][1]);
        cb[(e0)     * Dd + d0 + 8] = __float2bfloat16(acc[nt][2]);
        cb[(e0 + 1) * Dd + d0 + 8] = __float2bfloat16(acc[nt][3]);
    }
}

// ---------------- attn apply (tensor core): out[e][n] = sum_d ctx_ed[e][d] q[d][n] ----------------
// per CTA: M=64(e), N=256(n), K=64(d). 8 warps: wm (m32) x wn (n64).
__global__ __launch_bounds__(256) void attn_apply_mma(const bf16* __restrict__ ctx_ed,
                                                      const bf16* __restrict__ qkv,
                                                      bf16* __restrict__ out)
{
    int n0 = blockIdx.x * 256, h = blockIdx.y, bt = blockIdx.z;
    const bf16* cbase = ctx_ed + ((long long)bt * HEADS + h) * (Dd * Dd);
    const bf16* qbase = qkv + (long long)bt * C3 * NN + (long long)(h * Dd) * NN;

    __shared__ bf16 Asm[64 * 64];    // [e][d]
    __shared__ bf16 Bsm[64 * 256];   // [d][n]
    uint32_t asb = smem_u32(&Asm[0]);
    uint32_t bsb = smem_u32(&Bsm[0]);

    int tid = threadIdx.x;
    int lane = tid & 31, warp = tid >> 5;
    int wm = warp >> 2, wn = warp & 3;

    #pragma unroll
    for (int i = 0; i < 2; i++) {
        int idx = i * 256 + tid;
        int row = idx >> 3, ch = idx & 7;
        const bf16* src = cbase + row * Dd + ch * 8;
        uint32_t dst = asb + row * 128 + ((ch ^ (row & 7)) << 4);
        CP_ASYNC(dst, src);
    }
    #pragma unroll
    for (int i = 0; i < 8; i++) {
        int idx = i * 256 + tid;
        int row = idx >> 5, ch = idx & 31;
        const bf16* src = qbase + (long long)row * NN + n0 + ch * 8;
        uint32_t dst = bsb + row * 512 + ((ch ^ (row & 7)) << 4);
        CP_ASYNC(dst, src);
    }
    CP_COMMIT();
    CP_WAIT0();
    __syncthreads();

    float acc[2][8][4] = {};
    #pragma unroll
    for (int ks = 0; ks < 4; ks++) {
        int k0 = ks * 16;
        uint32_t af[2][4];
        #pragma unroll
        for (int mt = 0; mt < 2; mt++) {
            int row = wm * 32 + mt * 16 + (lane & 15);
            int ch  = (k0 >> 3) + (lane >> 4);
            uint32_t addr = asb + row * 128 + ((ch ^ (row & 7)) << 4);
            LDSM_X4(af[mt][0], af[mt][1], af[mt][2], af[mt][3], addr);
        }
        #pragma unroll
        for (int nt = 0; nt < 8; nt++) {
            int krow = k0 + (lane & 15);
            int ncol = wn * 64 + nt * 8;
            uint32_t addr = bsb + krow * 512 + (((ncol >> 3) ^ (krow & 7)) << 4);
            uint32_t b0, b1;
            LDSM_X2T(b0, b1, addr);
            #pragma unroll
            for (int mt = 0; mt < 2; mt++)
                MMA16816(acc[mt][nt][0], acc[mt][nt][1], acc[mt][nt][2], acc[mt][nt][3],
                         af[mt][0], af[mt][1], af[mt][2], af[mt][3], b0, b1);
        }
    }

    bf16* ob = out + (long long)bt * Cc * NN + (long long)(h * Dd) * NN;
    int g4 = lane >> 2, t4 = lane & 3;
    #pragma unroll
    for (int mt = 0; mt < 2; mt++) {
        #pragma unroll
        for (int nt = 0; nt < 8; nt++) {
            int erow = wm * 32 + mt * 16 + g4;
            int col  = n0 + wn * 64 + nt * 8 + t4 * 2;
            float* a = acc[mt][nt];
            __nv_bfloat162 v0 = __floats2bfloat162_rn(a[0], a[1]);
            __nv_bfloat162 v1 = __floats2bfloat162_rn(a[2], a[3]);
            *reinterpret_cast<__nv_bfloat162*>(ob + (long long)erow * NN + col) = v0;
            *reinterpret_cast<__nv_bfloat162*>(ob + (long long)(erow + 8) * NN + col) = v1;
        }
    }
}

// ---------------- temporal attention (bf16 qkv) ----------------
#define ST 8
__global__ __launch_bounds__(128) void temporal_sim(const bf16* __restrict__ tqkv,
                                                    float* __restrict__ attn)
{
    int b = blockIdx.z, hh = blockIdx.y;
    int s0 = blockIdx.x * ST;
    __shared__ float ks[16 * 64 * (ST + 1)];
    const bf16* kb = tqkv + ((long long)b * C3 + Cc + hh * Dd) * (Tt * NN);
    int tid = threadIdx.x;
    #pragma unroll
    for (int l = 0; l < (16 * 64 * ST) / 128; l++) {
        int idx = l * 128 + tid;
        int s = idx & (ST - 1);
        int rest = idx >> 3;
        int d = rest & 63, j = rest >> 6;
        ks[rest * (ST + 1) + s] = __bfloat162float(kb[(long long)d * (Tt * NN) + j * NN + s0 + s]);
    }
    __syncthreads();
    int sl = tid & (ST - 1);
    int i  = tid >> 3;
    const bf16* qb = tqkv + ((long long)b * C3 + hh * Dd) * (Tt * NN) + (long long)i * NN + s0 + sl;
    float acc[16];
    #pragma unroll
    for (int j = 0; j < 16; j++) acc[j] = 0.f;
    for (int d = 0; d < 64; d++) {
        float qv = __bfloat162float(qb[(long long)d * (Tt * NN)]) * 0.125f;
        #pragma unroll
        for (int j = 0; j < 16; j++)
            acc[j] += qv * ks[(j * 64 + d) * (ST + 1) + sl];
    }
    float m = acc[0];
    #pragma unroll
    for (int j = 1; j < 16; j++) m = fmaxf(m, acc[j]);
    float sum = 0.f;
    #pragma unroll
    for (int j = 0; j < 16; j++) { acc[j] = __expf(acc[j] - m); sum += acc[j]; }
    float inv = 1.f / sum;
    float* ab = attn + (((long long)b * HEADS + hh) * Tt + i) * Tt * NN + s0 + sl;
    #pragma unroll
    for (int j = 0; j < 16; j++)
        ab[(long long)j * NN] = acc[j] * inv;
}

__global__ __launch_bounds__(128) void temporal_out(const bf16* __restrict__ tqkv,
                                                    const float* __restrict__ attn,
                                                    bf16* __restrict__ out)
{
    int b = blockIdx.z, hh = blockIdx.y;
    int s0 = blockIdx.x * ST;
    __shared__ float vs[16 * 64 * (ST + 1)];
    const bf16* vb = tqkv + ((long long)b * C3 + 2 * Cc + hh * Dd) * (Tt * NN);
    int tid = threadIdx.x;
    #pragma unroll
    for (int l = 0; l < (16 * 64 * ST) / 128; l++) {
        int idx = l * 128 + tid;
        int s = idx & (ST - 1);
        int rest = idx >> 3;
        int d = rest & 63, j = rest >> 6;
        vs[rest * (ST + 1) + s] = __bfloat162float(vb[(long long)d * (Tt * NN) + j * NN + s0 + s]);
    }
    __syncthreads();
    int sl = tid & (ST - 1);
    int dg = tid >> 3;
    const float* ab = attn + ((long long)b * HEADS + hh) * (Tt * Tt) * NN + s0 + sl;
    bf16* ob = out + ((long long)b * Cc + hh * Dd + dg * 4) * (Tt * NN) + s0 + sl;
    for (int i = 0; i < 16; i++) {
        float a0 = 0.f, a1 = 0.f, a2 = 0.f, a3 = 0.f;
        #pragma unroll
        for (int j = 0; j < 16; j++) {
            float av = ab[(long long)(i * 16 + j) * NN];
            a0 += av * vs[(j * 64 + dg * 4 + 0) * (ST + 1) + sl];
            a1 += av * vs[(j * 64 + dg * 4 + 1) * (ST + 1) + sl];
            a2 += av * vs[(j * 64 + dg * 4 + 2) * (ST + 1) + sl];
            a3 += av * vs[(j * 64 + dg * 4 + 3) * (ST + 1) + sl];
        }
        long long t_off = (long long)i * NN;
        ob[t_off + 0 * (long long)(Tt * NN)] = __float2bfloat16(a0);
        ob[t_off + 1 * (long long)(Tt * NN)] = __float2bfloat16(a1);
        ob[t_off + 2 * (long long)(Tt * NN)] = __float2bfloat16(a2);
        ob[t_off + 3 * (long long)(Tt * NN)] = __float2bfloat16(a3);
    }
}

// ---------------- launch ----------------
extern "C" void kernel_launch(void* const* d_in, const int* in_sizes, int n_in,
                              void* d_out, int out_size)
{
    const float* x      = (const float*)d_in[0];
    const float* w_sqkv = (const float*)d_in[1];
    const float* w_sout = (const float*)d_in[2];
    const float* b_sout = (const float*)d_in[3];
    const float* w_tqkv = (const float*)d_in[4];
    const float* w_tout = (const float*)d_in[5];
    float* out = (float*)d_out;

    bf16 *wsqkv_t, *wsout_t, *wtqkv_t, *wtout_t, *xbf, *sqkv, *ctx_ed, *sattn_bf, *h1_bf, *tqkv, *tout_bf;
    float *attnw;
    cudaGetSymbolAddress((void**)&wsqkv_t, g_wsqkv_t);
    cudaGetSymbolAddress((void**)&wsout_t, g_wsout_t);
    cudaGetSymbolAddress((void**)&wtqkv_t, g_wtqkv_t);
    cudaGetSymbolAddress((void**)&wtout_t, g_wtout_t);
    cudaGetSymbolAddress((void**)&xbf,     g_xbf);
    cudaGetSymbolAddress((void**)&sqkv,    g_sqkv);
    cudaGetSymbolAddress((void**)&ctx_ed,  g_ctx_ed);
    cudaGetSymbolAddress((void**)&sattn_bf,g_sattn_bf);
    cudaGetSymbolAddress((void**)&h1_bf,   g_h1_bf);
    cudaGetSymbolAddress((void**)&tqkv,    g_tqkv);
    cudaGetSymbolAddress((void**)&attnw,   g_attnw);
    cudaGetSymbolAddress((void**)&tout_bf, g_tout_bf);

    const long long TN = (long long)Tt * NN;
    const long long XB = (long long)Cc * TN;

    int xN = Bb * Cc * Tt * NN;
    f2b_kernel<<<(xN / 4 + 255) / 256, 256>>>(x, xbf, xN);
    transpose_w_kernel<<<(C3 * Cc + 255) / 256, 256>>>(w_sqkv, wsqkv_t, C3, Cc);
    transpose_w_kernel<<<(Cc * Cc + 255) / 256, 256>>>(w_sout, wsout_t, Cc, Cc);
    transpose_w_kernel<<<(C3 * Cc + 255) / 256, 256>>>(w_tqkv, wtqkv_t, C3, Cc);
    transpose_w_kernel<<<(Cc * Cc + 255) / 256, 256>>>(w_tout, wtout_t, Cc, Cc);

    // 1) spatial qkv -> sqkv (bf16) [bt][o][n]
    gemm_bf16<<<dim3(NN / 128, C3 / 128, BT), 256>>>(
        wsqkv_t, xbf, nullptr, sqkv, nullptr, nullptr,
        Cc, C3, Tt,
        XB, NN, TN,
        (long long)Tt * C3 * NN, (long long)C3 * NN, NN);

    // 2-3) softmaxes (bf16)
    softmax_q<<<dim3(NN / 128, HEADS, BT), 128>>>(sqkv);
    softmax_k<<<dim3(Cc, BT), 256>>>(sqkv);

    // 4) ctx (tensor core) -> ctx_ed bf16 [e][d]
    ctx_mma<<<dim3(HEADS, BT), 128>>>(sqkv, ctx_ed);

    // 5) apply (tensor core) -> sattn bf16
    attn_apply_mma<<<dim3(NN / 256, HEADS, BT), 256>>>(ctx_ed, sqkv, sattn_bf);

    // 6) spatial proj + bias -> h1 bf16 [b][o][t][n]
    gemm_bf16<<<dim3(NN / 128, Cc / 128, BT), 256>>>(
        wsout_t, sattn_bf, nullptr, h1_bf, b_sout, nullptr,
        Cc, Cc, Tt,
        (long long)Tt * Cc * NN, (long long)Cc * NN, NN,
        XB, NN, TN);

    // 7) temporal qkv -> tqkv bf16 [b][o][tn]
    gemm_bf16<<<dim3((int)(TN / 128), C3 / 128, Bb), 256>>>(
        wtqkv_t, h1_bf, nullptr, tqkv, nullptr, nullptr,
        Cc, C3, 1,
        XB, 0, TN,
        (long long)C3 * TN, 0, TN);

    // 8-9) temporal attention
    temporal_sim<<<dim3(NN / ST, HEADS, Bb), 128>>>(tqkv, attnw);
    temporal_out<<<dim3(NN / ST, HEADS, Bb), 128>>>(tqkv, attnw, tout_bf);

    // 10) temporal proj + residual -> out fp32
    gemm_bf16<<<dim3((int)(TN / 128), Cc / 128, Bb), 256>>>(
        wtout_t, tout_bf, out, nullptr, nullptr, x,
        Cc, Cc, 1,
        XB, 0, TN,
        XB, 0, TN);
}